// round 6
// baseline (speedup 1.0000x reference)
#include <cuda_runtime.h>
#include <cstdint>

#define N_NODES 100000
#define N_EDGES 800000
#define HID     128
#define NGRAPH  128
#define NCLS    10
#define BN_EPS  1e-5f
#define MT      128        // M rows per MLP block tile
#define SA      132        // smem stride (floats), conflict-free for fragment gathers

// ---------------- scratch (allocation-free: device globals) ----------------
__device__ __align__(16) float g_agg[N_NODES * HID];   // self + neighbor sum
__device__ __align__(16) float g_h  [N_NODES * HID];   // conv output / BN output
__device__ __align__(16) float g_stats[4 * HID];       // [sum1, sumsq1, sum2, sumsq2]
__device__ __align__(16) float g_pool[NGRAPH * HID];
__device__            float g_cnt[NGRAPH];
__device__ int g_idx64;
__device__ int g_batch64;
// CSR scratch
__device__ int g_deg[N_NODES];
__device__ int g_rowptr[N_NODES + 1];
__device__ int g_cursor[N_NODES];
__device__ int g_esrc[N_EDGES];

// ---------------- helpers ----------------
__device__ __forceinline__ uint32_t f2tf(float f) {
    uint32_t u;
    asm("cvt.rna.tf32.f32 %0, %1;" : "=r"(u) : "f"(f));
    return u;
}
__device__ __forceinline__ void mma_tf32(float* c, const uint32_t* a, const uint32_t* b) {
    asm volatile(
        "mma.sync.aligned.m16n8k8.row.col.f32.tf32.tf32.f32 "
        "{%0,%1,%2,%3}, {%4,%5,%6,%7}, {%8,%9}, {%0,%1,%2,%3};"
        : "+f"(c[0]), "+f"(c[1]), "+f"(c[2]), "+f"(c[3])
        : "r"(a[0]), "r"(a[1]), "r"(a[2]), "r"(a[3]), "r"(b[0]), "r"(b[1]));
}

// ---------------- dtype detection ----------------
__global__ void detect_kernel(const void* eidx, const void* batch) {
    if (threadIdx.x == 0) {
        const long long* p = (const long long*)eidx;
        int ok = 1;
        for (int i = 0; i < 64; i++) { long long v = p[i]; if (v < 0 || v >= N_NODES) { ok = 0; break; } }
        g_idx64 = ok;
        const long long* q = (const long long*)batch;
        int ok2 = 1;
        for (int i = N_NODES / 2 - 64; i < N_NODES / 2; i++) { long long v = q[i]; if (v < 0 || v >= NGRAPH) { ok2 = 0; break; } }
        g_batch64 = ok2;
    }
}
__device__ __forceinline__ int load_index(const void* p, unsigned i, int is64) {
    return is64 ? (int)((const long long*)p)[i] : ((const int*)p)[i];
}

__global__ void zero_kernel() {
    int i = blockIdx.x * blockDim.x + threadIdx.x;
    if (i < NGRAPH * HID) g_pool[i] = 0.f;
    if (i < 4 * HID)      g_stats[i] = 0.f;
    if (i < NGRAPH)       g_cnt[i] = 0.f;
    if (i < N_NODES)      g_deg[i] = 0;
}

// ================= CSR build (once per launch; graph shared by both convs) =================
__global__ void hist_kernel(const void* __restrict__ eidx) {
    int e = blockIdx.x * 256 + threadIdx.x;
    if (e >= N_EDGES) return;
    int d = load_index(eidx, N_EDGES + (unsigned)e, g_idx64);
    atomicAdd(&g_deg[d], 1);
}

// single-block exclusive scan of g_deg -> g_rowptr (+ copy to g_cursor)
#define SCAN_T 1024
#define SCAN_CH ((N_NODES + SCAN_T - 1) / SCAN_T)   // 98
__global__ void scan_kernel() {
    __shared__ int ssum[SCAN_T];
    int t = threadIdx.x;
    int base = t * SCAN_CH;
    int lim = min(base + SCAN_CH, N_NODES);
    int s = 0;
    for (int i = base; i < lim; i++) s += g_deg[i];
    ssum[t] = s;
    __syncthreads();
    // Hillis-Steele inclusive scan on 1024 partials
    for (int off = 1; off < SCAN_T; off <<= 1) {
        int v = (t >= off) ? ssum[t - off] : 0;
        __syncthreads();
        ssum[t] += v;
        __syncthreads();
    }
    int run = (t == 0) ? 0 : ssum[t - 1];
    for (int i = base; i < lim; i++) {
        g_rowptr[i] = run;
        g_cursor[i] = run;
        run += g_deg[i];
    }
    if (t == SCAN_T - 1) g_rowptr[N_NODES] = ssum[SCAN_T - 1];
}

__global__ void fill_kernel(const void* __restrict__ eidx) {
    int e = blockIdx.x * 256 + threadIdx.x;
    if (e >= N_EDGES) return;
    int is64 = g_idx64;
    int s = load_index(eidx, (unsigned)e, is64);
    int d = load_index(eidx, N_EDGES + (unsigned)e, is64);
    int pos = atomicAdd(&g_cursor[d], 1);
    g_esrc[pos] = s;
}

// ================= gather aggregation: out[d] = feat[d] + sum_{j in CSR(d)} feat[src_j] ====
// one warp per destination node; lane = one float4 column
__global__ void gather_kernel(const float* __restrict__ feat, float* __restrict__ out) {
    int n = blockIdx.x * 8 + (threadIdx.x >> 5);
    if (n >= N_NODES) return;
    int lane = threadIdx.x & 31;
    const float4* f4 = (const float4*)feat;
    float4 acc = __ldg(&f4[(size_t)n * 32 + lane]);   // self term
    int beg = g_rowptr[n], end = g_rowptr[n + 1];
    for (int j = beg; j < end; j++) {
        int s = g_esrc[j];
        float4 v = __ldg(&f4[(size_t)s * 32 + lane]);
        acc.x += v.x; acc.y += v.y; acc.z += v.z; acc.w += v.w;
    }
    ((float4*)out)[(size_t)n * 32 + lane] = acc;
}

// ================= fused MLP: C = relu(A@Wa + ba)@Wb + bb  (mma.sync tf32) =================
__device__ __forceinline__ void warp_gemm_tf32(const float* __restrict__ sAp,
                                               const float* __restrict__ sW,
                                               int wm, int wn, int g, int tg,
                                               float acc[2][8][4])
{
#pragma unroll 4
    for (int kt = 0; kt < 16; kt++) {
        int k0 = kt * 8;
        uint32_t a[2][4];
#pragma unroll
        for (int mi = 0; mi < 2; mi++) {
            int r = wm + mi * 16 + g;
            a[mi][0] = __float_as_uint(sAp[(r    ) * SA + k0 + tg    ]);
            a[mi][1] = __float_as_uint(sAp[(r + 8) * SA + k0 + tg    ]);
            a[mi][2] = __float_as_uint(sAp[(r    ) * SA + k0 + tg + 4]);
            a[mi][3] = __float_as_uint(sAp[(r + 8) * SA + k0 + tg + 4]);
        }
        uint32_t b[8][2];
#pragma unroll
        for (int ni = 0; ni < 8; ni++) {
            int n = wn + ni * 8 + g;
            b[ni][0] = __float_as_uint(sW[(k0 + tg    ) * SA + n]);
            b[ni][1] = __float_as_uint(sW[(k0 + tg + 4) * SA + n]);
        }
#pragma unroll
        for (int mi = 0; mi < 2; mi++)
#pragma unroll
            for (int ni = 0; ni < 8; ni++)
                mma_tf32(acc[mi][ni], a[mi], b[ni]);
    }
}

__global__ void __launch_bounds__(256, 1) mlp_kernel(
    const float* __restrict__ A, const float* __restrict__ Wa, const float* __restrict__ ba,
    const float* __restrict__ Wb, const float* __restrict__ bb, float* __restrict__ C)
{
    extern __shared__ float sm[];
    float* sAp = sm;
    float* sWa = sm + 128 * SA;
    float* sWb = sWa + 128 * SA;
    float* sBa = sWb + 128 * SA;
    float* sBb = sBa + 128;

    int t = threadIdx.x;
    int wid = t >> 5, lane = t & 31, g = lane >> 2, tg = lane & 3;
    int wm = (wid & 3) * 32, wn = (wid >> 2) * 64;
    int row0 = blockIdx.x * MT;

    if (t < 128) { sBa[t] = ba[t]; sBb[t] = bb[t]; }

    {
        const float4* A4  = (const float4*)A;
        const float4* Wa4 = (const float4*)Wa;
        const float4* Wb4 = (const float4*)Wb;
#pragma unroll
        for (int i = 0; i < 16; i++) {
            int idx = t + i * 256;
            int r = idx >> 5, c4 = idx & 31;
            float4 v = (row0 + r < N_NODES) ? A4[(size_t)(row0 + r) * 32 + c4]
                                            : make_float4(0.f, 0.f, 0.f, 0.f);
            *(uint4*)&sAp[r * SA + c4 * 4] = make_uint4(f2tf(v.x), f2tf(v.y), f2tf(v.z), f2tf(v.w));
            float4 wa = Wa4[idx];
            *(uint4*)&sWa[r * SA + c4 * 4] = make_uint4(f2tf(wa.x), f2tf(wa.y), f2tf(wa.z), f2tf(wa.w));
            float4 wb = Wb4[idx];
            *(uint4*)&sWb[r * SA + c4 * 4] = make_uint4(f2tf(wb.x), f2tf(wb.y), f2tf(wb.z), f2tf(wb.w));
        }
    }
    __syncthreads();

    float acc[2][8][4];
#pragma unroll
    for (int mi = 0; mi < 2; mi++)
#pragma unroll
        for (int ni = 0; ni < 8; ni++)
#pragma unroll
            for (int q = 0; q < 4; q++) acc[mi][ni][q] = 0.f;

    warp_gemm_tf32(sAp, sWa, wm, wn, g, tg, acc);
    __syncthreads();

#pragma unroll
    for (int mi = 0; mi < 2; mi++) {
        int r0 = wm + mi * 16 + g;
#pragma unroll
        for (int ni = 0; ni < 8; ni++) {
            int c0 = wn + ni * 8 + 2 * tg;
            float bx = sBa[c0], by = sBa[c0 + 1];
            sAp[(r0    ) * SA + c0    ] = __uint_as_float(f2tf(fmaxf(acc[mi][ni][0] + bx, 0.f)));
            sAp[(r0    ) * SA + c0 + 1] = __uint_as_float(f2tf(fmaxf(acc[mi][ni][1] + by, 0.f)));
            sAp[(r0 + 8) * SA + c0    ] = __uint_as_float(f2tf(fmaxf(acc[mi][ni][2] + bx, 0.f)));
            sAp[(r0 + 8) * SA + c0 + 1] = __uint_as_float(f2tf(fmaxf(acc[mi][ni][3] + by, 0.f)));
        }
    }
    __syncthreads();

#pragma unroll
    for (int mi = 0; mi < 2; mi++)
#pragma unroll
        for (int ni = 0; ni < 8; ni++)
#pragma unroll
            for (int q = 0; q < 4; q++) acc[mi][ni][q] = 0.f;

    warp_gemm_tf32(sAp, sWb, wm, wn, g, tg, acc);

#pragma unroll
    for (int mi = 0; mi < 2; mi++) {
        int r0 = wm + mi * 16 + g;
#pragma unroll
        for (int ni = 0; ni < 8; ni++) {
            int c0 = wn + ni * 8 + 2 * tg;
            float bx = sBb[c0], by = sBb[c0 + 1];
            int rg0 = row0 + r0, rg1 = row0 + r0 + 8;
            if (rg0 < N_NODES) {
                float2 o = make_float2(acc[mi][ni][0] + bx, acc[mi][ni][1] + by);
                *(float2*)&C[(size_t)rg0 * HID + c0] = o;
            }
            if (rg1 < N_NODES) {
                float2 o = make_float2(acc[mi][ni][2] + bx, acc[mi][ni][3] + by);
                *(float2*)&C[(size_t)rg1 * HID + c0] = o;
            }
        }
    }
}

// ================= BN / stats / pool / head =================
__global__ void colstats_kernel(const float* __restrict__ h, int stat_off) {
    int f = threadIdx.x;
    float s = 0.f, q = 0.f;
    for (int r = blockIdx.x; r < N_NODES; r += gridDim.x) {
        float v = h[(size_t)r * HID + f];
        s += v; q += v * v;
    }
    atomicAdd(&g_stats[stat_off + f], s);
    atomicAdd(&g_stats[stat_off + HID + f], q);
}

__global__ void bn_apply1_kernel(const float* __restrict__ gamma, const float* __restrict__ beta) {
    int i = blockIdx.x * 256 + threadIdx.x;
    if (i >= N_NODES * 32) return;
    int c4 = i & 31;
    const float inv_n = 1.f / (float)N_NODES;
    float4 sum4 = ((const float4*)g_stats)[c4];
    float4 sq4  = ((const float4*)g_stats)[32 + c4];
    float4 gm4  = ((const float4*)gamma)[c4];
    float4 bt4  = ((const float4*)beta)[c4];
    float4 v = ((float4*)g_h)[i];
    float4 y;
    float m = sum4.x * inv_n, var = sq4.x * inv_n - m * m;
    y.x = fmaxf((v.x - m) * rsqrtf(var + BN_EPS) * gm4.x + bt4.x, 0.f);
    m = sum4.y * inv_n; var = sq4.y * inv_n - m * m;
    y.y = fmaxf((v.y - m) * rsqrtf(var + BN_EPS) * gm4.y + bt4.y, 0.f);
    m = sum4.z * inv_n; var = sq4.z * inv_n - m * m;
    y.z = fmaxf((v.z - m) * rsqrtf(var + BN_EPS) * gm4.z + bt4.z, 0.f);
    m = sum4.w * inv_n; var = sq4.w * inv_n - m * m;
    y.w = fmaxf((v.w - m) * rsqrtf(var + BN_EPS) * gm4.w + bt4.w, 0.f);
    ((float4*)g_h)[i] = y;
}

__global__ void bn_apply2_kernel(const float* __restrict__ gamma, const float* __restrict__ beta,
                                 const void* __restrict__ batch) {
    int i = blockIdx.x * 256 + threadIdx.x;
    if (i >= N_NODES * 32) return;
    int c4 = i & 31;
    int row = i >> 5;
    const float inv_n = 1.f / (float)N_NODES;
    float4 sum4 = ((const float4*)g_stats)[64 + c4];
    float4 sq4  = ((const float4*)g_stats)[96 + c4];
    float4 gm4  = ((const float4*)gamma)[c4];
    float4 bt4  = ((const float4*)beta)[c4];
    float4 v = ((float4*)g_h)[i];
    float4 y;
    float m = sum4.x * inv_n, var = sq4.x * inv_n - m * m;
    y.x = fmaxf((v.x - m) * rsqrtf(var + BN_EPS) * gm4.x + bt4.x, 0.f);
    m = sum4.y * inv_n; var = sq4.y * inv_n - m * m;
    y.y = fmaxf((v.y - m) * rsqrtf(var + BN_EPS) * gm4.y + bt4.y, 0.f);
    m = sum4.z * inv_n; var = sq4.z * inv_n - m * m;
    y.z = fmaxf((v.z - m) * rsqrtf(var + BN_EPS) * gm4.z + bt4.z, 0.f);
    m = sum4.w * inv_n; var = sq4.w * inv_n - m * m;
    y.w = fmaxf((v.w - m) * rsqrtf(var + BN_EPS) * gm4.w + bt4.w, 0.f);
    int b = load_index(batch, (unsigned)row, g_batch64);
    atomicAdd(((float4*)g_pool) + (b * 32 + c4), y);
}

__global__ void counts_kernel(const void* __restrict__ batch) {
    __shared__ int hist[NGRAPH];
    if (threadIdx.x < NGRAPH) hist[threadIdx.x] = 0;
    __syncthreads();
    int is64 = g_batch64;
    for (int i = blockIdx.x * 256 + threadIdx.x; i < N_NODES; i += gridDim.x * 256)
        atomicAdd(&hist[load_index(batch, (unsigned)i, is64)], 1);
    __syncthreads();
    if (threadIdx.x < NGRAPH && hist[threadIdx.x])
        atomicAdd(&g_cnt[threadIdx.x], (float)hist[threadIdx.x]);
}

__global__ void head_kernel(const float* __restrict__ Wlin, const float* __restrict__ blin,
                            float* __restrict__ out) {
    __shared__ float p[HID];
    __shared__ float logit[NCLS];
    int g = blockIdx.x;
    float c = fmaxf(g_cnt[g], 1.0f);
    p[threadIdx.x] = g_pool[g * HID + threadIdx.x] / c;
    __syncthreads();
    if (threadIdx.x < NCLS) {
        float s = blin[threadIdx.x];
        for (int k = 0; k < HID; k++) s += p[k] * Wlin[k * NCLS + threadIdx.x];
        logit[threadIdx.x] = s;
    }
    __syncthreads();
    if (threadIdx.x == 0) {
        float m = -1e30f;
        for (int i = 0; i < NCLS; i++) m = fmaxf(m, logit[i]);
        float se = 0.f;
        for (int i = 0; i < NCLS; i++) se += expf(logit[i] - m);
        float lse = m + logf(se);
        for (int i = 0; i < NCLS; i++) out[g * NCLS + i] = logit[i] - lse;
    }
}

// ================= launch =================
extern "C" void kernel_launch(void* const* d_in, const int* in_sizes, int n_in,
                              void* d_out, int out_size) {
    const float* x     = (const float*)d_in[0];
    const void*  eidx  = d_in[1];
    const void*  batch = d_in[2];
    const float* W1a = (const float*)d_in[3];
    const float* b1a = (const float*)d_in[4];
    const float* W1b = (const float*)d_in[5];
    const float* b1b = (const float*)d_in[6];
    const float* gamma1 = (const float*)d_in[7];
    const float* beta1  = (const float*)d_in[8];
    const float* W2a = (const float*)d_in[9];
    const float* b2a = (const float*)d_in[10];
    const float* W2b = (const float*)d_in[11];
    const float* b2b = (const float*)d_in[12];
    const float* gamma2 = (const float*)d_in[13];
    const float* beta2  = (const float*)d_in[14];
    const float* Wlin = (const float*)d_in[15];
    const float* blin = (const float*)d_in[16];
    float* out = (float*)d_out;

    float *p_agg, *p_h;
    cudaGetSymbolAddress((void**)&p_agg, g_agg);
    cudaGetSymbolAddress((void**)&p_h,   g_h);

    const int SMEM_MLP = (3 * 128 * SA + 256) * sizeof(float);   // ~204 KB
    cudaFuncSetAttribute(mlp_kernel, cudaFuncAttributeMaxDynamicSharedMemorySize, SMEM_MLP);

    const int EW_BLOCKS  = (N_NODES * 32 + 255) / 256;
    const int EDGE_BLOCKS = (N_EDGES + 255) / 256;
    const int MLP_BLOCKS = (N_NODES + MT - 1) / MT;
    const int GATHER_BLOCKS = (N_NODES + 7) / 8;

    detect_kernel<<<1, 32>>>(eidx, batch);
    zero_kernel<<<(N_NODES + 255) / 256, 256>>>();

    // ---- CSR build (once; shared by both convs) ----
    hist_kernel<<<EDGE_BLOCKS, 256>>>(eidx);
    scan_kernel<<<1, SCAN_T>>>();
    fill_kernel<<<EDGE_BLOCKS, 256>>>(eidx);

    // ---- conv1 ----
    gather_kernel<<<GATHER_BLOCKS, 256>>>(x, p_agg);
    mlp_kernel<<<MLP_BLOCKS, 256, SMEM_MLP>>>(p_agg, W1a, b1a, W1b, b1b, p_h);
    colstats_kernel<<<1024, 128>>>(p_h, 0);
    bn_apply1_kernel<<<EW_BLOCKS, 256>>>(gamma1, beta1);

    // ---- conv2 ----
    gather_kernel<<<GATHER_BLOCKS, 256>>>(p_h, p_agg);
    mlp_kernel<<<MLP_BLOCKS, 256, SMEM_MLP>>>(p_agg, W2a, b2a, W2b, b2b, p_h);
    colstats_kernel<<<1024, 128>>>(p_h, 2 * HID);
    counts_kernel<<<128, 256>>>(batch);
    bn_apply2_kernel<<<EW_BLOCKS, 256>>>(gamma2, beta2, batch);

    // ---- head ----
    head_kernel<<<NGRAPH, HID>>>(Wlin, blin, out);
}

// round 7
// speedup vs baseline: 1.4041x; 1.4041x over previous
#include <cuda_runtime.h>
#include <cstdint>

#define N_NODES 100000
#define N_EDGES 800000
#define HID     128
#define NGRAPH  128
#define NCLS    10
#define BN_EPS  1e-5f
#define MT      128        // M rows per MLP block tile
#define SA      132        // smem stride (floats), conflict-free for fragment gathers
#define CHUNK   1024
#define NCHUNK  ((N_NODES + CHUNK - 1) / CHUNK)   // 98

// ---------------- scratch (allocation-free: device globals) ----------------
__device__ __align__(16) float g_agg[N_NODES * HID];   // self + neighbor sum
__device__ __align__(16) float g_h  [N_NODES * HID];   // conv output / BN output
__device__ __align__(16) float g_stats[4 * HID];       // [sum1, sumsq1, sum2, sumsq2]
__device__ __align__(16) float g_pool[NGRAPH * HID];
__device__            float g_cnt[NGRAPH];
__device__ int g_idx64;
__device__ int g_batch64;
// CSR scratch
__device__ int g_deg[N_NODES];
__device__ int g_rowptr[N_NODES + 1];
__device__ int g_cursor[N_NODES];
__device__ int g_esrc[N_EDGES];
__device__ int g_bsum[NCHUNK];
__device__ int g_boff[NCHUNK];

// ---------------- helpers ----------------
__device__ __forceinline__ uint32_t f2tf(float f) {
    uint32_t u;
    asm("cvt.rna.tf32.f32 %0, %1;" : "=r"(u) : "f"(f));
    return u;
}
__device__ __forceinline__ void mma_tf32(float* c, const uint32_t* a, const uint32_t* b) {
    asm volatile(
        "mma.sync.aligned.m16n8k8.row.col.f32.tf32.tf32.f32 "
        "{%0,%1,%2,%3}, {%4,%5,%6,%7}, {%8,%9}, {%0,%1,%2,%3};"
        : "+f"(c[0]), "+f"(c[1]), "+f"(c[2]), "+f"(c[3])
        : "r"(a[0]), "r"(a[1]), "r"(a[2]), "r"(a[3]), "r"(b[0]), "r"(b[1]));
}

// ---------------- dtype detection ----------------
__global__ void detect_kernel(const void* eidx, const void* batch) {
    if (threadIdx.x == 0) {
        const long long* p = (const long long*)eidx;
        int ok = 1;
        for (int i = 0; i < 64; i++) { long long v = p[i]; if (v < 0 || v >= N_NODES) { ok = 0; break; } }
        g_idx64 = ok;
        const long long* q = (const long long*)batch;
        int ok2 = 1;
        for (int i = N_NODES / 2 - 64; i < N_NODES / 2; i++) { long long v = q[i]; if (v < 0 || v >= NGRAPH) { ok2 = 0; break; } }
        g_batch64 = ok2;
    }
}
__device__ __forceinline__ int load_index(const void* p, unsigned i, int is64) {
    return is64 ? (int)((const long long*)p)[i] : ((const int*)p)[i];
}

__global__ void zero_kernel() {
    int i = blockIdx.x * blockDim.x + threadIdx.x;
    if (i < NGRAPH * HID) g_pool[i] = 0.f;
    if (i < 4 * HID)      g_stats[i] = 0.f;
    if (i < NGRAPH)       g_cnt[i] = 0.f;
    if (i < N_NODES)      g_deg[i] = 0;
}

// ================= CSR build (once per launch; graph shared by both convs) =================
__global__ void hist_kernel(const void* __restrict__ eidx) {
    int e = blockIdx.x * 256 + threadIdx.x;
    if (e >= N_EDGES) return;
    int d = load_index(eidx, N_EDGES + (unsigned)e, g_idx64);
    atomicAdd(&g_deg[d], 1);
}

// phase 1: per-chunk degree sums (98 blocks x 256 thr)
__global__ void chunksum_kernel() {
    __shared__ int red[256];
    int b = blockIdx.x, t = threadIdx.x;
    int base = b * CHUNK;
    int s = 0;
#pragma unroll
    for (int i = 0; i < CHUNK / 256; i++) {
        int idx = base + t + i * 256;
        if (idx < N_NODES) s += g_deg[idx];
    }
    red[t] = s;
    __syncthreads();
#pragma unroll
    for (int off = 128; off > 0; off >>= 1) {
        if (t < off) red[t] += red[t + off];
        __syncthreads();
    }
    if (t == 0) g_bsum[b] = red[0];
}

// phase 2: scan 98 chunk sums (1 block x 128 thr)
__global__ void bscan_kernel() {
    __shared__ int sb[128];
    int t = threadIdx.x;
    sb[t] = (t < NCHUNK) ? g_bsum[t] : 0;
    __syncthreads();
#pragma unroll
    for (int off = 1; off < 128; off <<= 1) {
        int v = (t >= off) ? sb[t - off] : 0;
        __syncthreads();
        sb[t] += v;
        __syncthreads();
    }
    if (t < NCHUNK) g_boff[t] = (t == 0) ? 0 : sb[t - 1];
    if (t == 0) g_rowptr[N_NODES] = N_EDGES;
}

// phase 3: in-chunk scan -> rowptr/cursor (98 blocks x 256 thr, 4 nodes/thread)
__global__ void chunkscan_kernel() {
    __shared__ int red[256];
    int b = blockIdx.x, t = threadIdx.x;
    int base = b * CHUNK + t * 4;
    int d[4], s = 0;
#pragma unroll
    for (int q = 0; q < 4; q++) {
        int idx = base + q;
        d[q] = (idx < N_NODES) ? g_deg[idx] : 0;
        s += d[q];
    }
    red[t] = s;
    __syncthreads();
#pragma unroll
    for (int off = 1; off < 256; off <<= 1) {
        int v = (t >= off) ? red[t - off] : 0;
        __syncthreads();
        red[t] += v;
        __syncthreads();
    }
    int run = g_boff[b] + ((t == 0) ? 0 : red[t - 1]);
#pragma unroll
    for (int q = 0; q < 4; q++) {
        int idx = base + q;
        if (idx < N_NODES) {
            g_rowptr[idx] = run;
            g_cursor[idx] = run;
            run += d[q];
        }
    }
}

__global__ void fill_kernel(const void* __restrict__ eidx) {
    int e = blockIdx.x * 256 + threadIdx.x;
    if (e >= N_EDGES) return;
    int is64 = g_idx64;
    int s = load_index(eidx, (unsigned)e, is64);
    int d = load_index(eidx, N_EDGES + (unsigned)e, is64);
    int pos = atomicAdd(&g_cursor[d], 1);
    g_esrc[pos] = s;
}

// ================= gather aggregation: out[d] = feat[d] + sum_{j in CSR(d)} feat[src_j] ====
// one warp per destination node; lane = one float4 column
__global__ void gather_kernel(const float* __restrict__ feat, float* __restrict__ out) {
    int n = blockIdx.x * 8 + (threadIdx.x >> 5);
    if (n >= N_NODES) return;
    int lane = threadIdx.x & 31;
    const float4* f4 = (const float4*)feat;
    float4 acc = __ldg(&f4[(size_t)n * 32 + lane]);   // self term
    int beg = g_rowptr[n], end = g_rowptr[n + 1];
    for (int j = beg; j < end; j++) {
        int s = g_esrc[j];
        float4 v = __ldg(&f4[(size_t)s * 32 + lane]);
        acc.x += v.x; acc.y += v.y; acc.z += v.z; acc.w += v.w;
    }
    ((float4*)out)[(size_t)n * 32 + lane] = acc;
}

// ================= fused MLP: C = relu(A@Wa + ba)@Wb + bb  (mma.sync tf32) =================
__device__ __forceinline__ void warp_gemm_tf32(const float* __restrict__ sAp,
                                               const float* __restrict__ sW,
                                               int wm, int wn, int g, int tg,
                                               float acc[2][8][4])
{
#pragma unroll 4
    for (int kt = 0; kt < 16; kt++) {
        int k0 = kt * 8;
        uint32_t a[2][4];
#pragma unroll
        for (int mi = 0; mi < 2; mi++) {
            int r = wm + mi * 16 + g;
            a[mi][0] = __float_as_uint(sAp[(r    ) * SA + k0 + tg    ]);
            a[mi][1] = __float_as_uint(sAp[(r + 8) * SA + k0 + tg    ]);
            a[mi][2] = __float_as_uint(sAp[(r    ) * SA + k0 + tg + 4]);
            a[mi][3] = __float_as_uint(sAp[(r + 8) * SA + k0 + tg + 4]);
        }
        uint32_t b[8][2];
#pragma unroll
        for (int ni = 0; ni < 8; ni++) {
            int n = wn + ni * 8 + g;
            b[ni][0] = __float_as_uint(sW[(k0 + tg    ) * SA + n]);
            b[ni][1] = __float_as_uint(sW[(k0 + tg + 4) * SA + n]);
        }
#pragma unroll
        for (int mi = 0; mi < 2; mi++)
#pragma unroll
            for (int ni = 0; ni < 8; ni++)
                mma_tf32(acc[mi][ni], a[mi], b[ni]);
    }
}

__global__ void __launch_bounds__(256, 1) mlp_kernel(
    const float* __restrict__ A, const float* __restrict__ Wa, const float* __restrict__ ba,
    const float* __restrict__ Wb, const float* __restrict__ bb, float* __restrict__ C)
{
    extern __shared__ float sm[];
    float* sAp = sm;
    float* sWa = sm + 128 * SA;
    float* sWb = sWa + 128 * SA;
    float* sBa = sWb + 128 * SA;
    float* sBb = sBa + 128;

    int t = threadIdx.x;
    int wid = t >> 5, lane = t & 31, g = lane >> 2, tg = lane & 3;
    int wm = (wid & 3) * 32, wn = (wid >> 2) * 64;
    int row0 = blockIdx.x * MT;

    if (t < 128) { sBa[t] = ba[t]; sBb[t] = bb[t]; }

    {
        const float4* A4  = (const float4*)A;
        const float4* Wa4 = (const float4*)Wa;
        const float4* Wb4 = (const float4*)Wb;
#pragma unroll
        for (int i = 0; i < 16; i++) {
            int idx = t + i * 256;
            int r = idx >> 5, c4 = idx & 31;
            float4 v = (row0 + r < N_NODES) ? A4[(size_t)(row0 + r) * 32 + c4]
                                            : make_float4(0.f, 0.f, 0.f, 0.f);
            *(uint4*)&sAp[r * SA + c4 * 4] = make_uint4(f2tf(v.x), f2tf(v.y), f2tf(v.z), f2tf(v.w));
            float4 wa = Wa4[idx];
            *(uint4*)&sWa[r * SA + c4 * 4] = make_uint4(f2tf(wa.x), f2tf(wa.y), f2tf(wa.z), f2tf(wa.w));
            float4 wb = Wb4[idx];
            *(uint4*)&sWb[r * SA + c4 * 4] = make_uint4(f2tf(wb.x), f2tf(wb.y), f2tf(wb.z), f2tf(wb.w));
        }
    }
    __syncthreads();

    float acc[2][8][4];
#pragma unroll
    for (int mi = 0; mi < 2; mi++)
#pragma unroll
        for (int ni = 0; ni < 8; ni++)
#pragma unroll
            for (int q = 0; q < 4; q++) acc[mi][ni][q] = 0.f;

    warp_gemm_tf32(sAp, sWa, wm, wn, g, tg, acc);
    __syncthreads();

#pragma unroll
    for (int mi = 0; mi < 2; mi++) {
        int r0 = wm + mi * 16 + g;
#pragma unroll
        for (int ni = 0; ni < 8; ni++) {
            int c0 = wn + ni * 8 + 2 * tg;
            float bx = sBa[c0], by = sBa[c0 + 1];
            sAp[(r0    ) * SA + c0    ] = __uint_as_float(f2tf(fmaxf(acc[mi][ni][0] + bx, 0.f)));
            sAp[(r0    ) * SA + c0 + 1] = __uint_as_float(f2tf(fmaxf(acc[mi][ni][1] + by, 0.f)));
            sAp[(r0 + 8) * SA + c0    ] = __uint_as_float(f2tf(fmaxf(acc[mi][ni][2] + bx, 0.f)));
            sAp[(r0 + 8) * SA + c0 + 1] = __uint_as_float(f2tf(fmaxf(acc[mi][ni][3] + by, 0.f)));
        }
    }
    __syncthreads();

#pragma unroll
    for (int mi = 0; mi < 2; mi++)
#pragma unroll
        for (int ni = 0; ni < 8; ni++)
#pragma unroll
            for (int q = 0; q < 4; q++) acc[mi][ni][q] = 0.f;

    warp_gemm_tf32(sAp, sWb, wm, wn, g, tg, acc);

#pragma unroll
    for (int mi = 0; mi < 2; mi++) {
        int r0 = wm + mi * 16 + g;
#pragma unroll
        for (int ni = 0; ni < 8; ni++) {
            int c0 = wn + ni * 8 + 2 * tg;
            float bx = sBb[c0], by = sBb[c0 + 1];
            int rg0 = row0 + r0, rg1 = row0 + r0 + 8;
            if (rg0 < N_NODES) {
                float2 o = make_float2(acc[mi][ni][0] + bx, acc[mi][ni][1] + by);
                *(float2*)&C[(size_t)rg0 * HID + c0] = o;
            }
            if (rg1 < N_NODES) {
                float2 o = make_float2(acc[mi][ni][2] + bx, acc[mi][ni][3] + by);
                *(float2*)&C[(size_t)rg1 * HID + c0] = o;
            }
        }
    }
}

// ================= BN / stats / pool / head =================
__global__ void colstats_kernel(const float* __restrict__ h, int stat_off) {
    int f = threadIdx.x;
    float s = 0.f, q = 0.f;
    for (int r = blockIdx.x; r < N_NODES; r += gridDim.x) {
        float v = h[(size_t)r * HID + f];
        s += v; q += v * v;
    }
    atomicAdd(&g_stats[stat_off + f], s);
    atomicAdd(&g_stats[stat_off + HID + f], q);
}

__global__ void bn_apply1_kernel(const float* __restrict__ gamma, const float* __restrict__ beta) {
    int i = blockIdx.x * 256 + threadIdx.x;
    if (i >= N_NODES * 32) return;
    int c4 = i & 31;
    const float inv_n = 1.f / (float)N_NODES;
    float4 sum4 = ((const float4*)g_stats)[c4];
    float4 sq4  = ((const float4*)g_stats)[32 + c4];
    float4 gm4  = ((const float4*)gamma)[c4];
    float4 bt4  = ((const float4*)beta)[c4];
    float4 v = ((float4*)g_h)[i];
    float4 y;
    float m = sum4.x * inv_n, var = sq4.x * inv_n - m * m;
    y.x = fmaxf((v.x - m) * rsqrtf(var + BN_EPS) * gm4.x + bt4.x, 0.f);
    m = sum4.y * inv_n; var = sq4.y * inv_n - m * m;
    y.y = fmaxf((v.y - m) * rsqrtf(var + BN_EPS) * gm4.y + bt4.y, 0.f);
    m = sum4.z * inv_n; var = sq4.z * inv_n - m * m;
    y.z = fmaxf((v.z - m) * rsqrtf(var + BN_EPS) * gm4.z + bt4.z, 0.f);
    m = sum4.w * inv_n; var = sq4.w * inv_n - m * m;
    y.w = fmaxf((v.w - m) * rsqrtf(var + BN_EPS) * gm4.w + bt4.w, 0.f);
    ((float4*)g_h)[i] = y;
}

__global__ void bn_apply2_kernel(const float* __restrict__ gamma, const float* __restrict__ beta,
                                 const void* __restrict__ batch) {
    int i = blockIdx.x * 256 + threadIdx.x;
    if (i >= N_NODES * 32) return;
    int c4 = i & 31;
    int row = i >> 5;
    const float inv_n = 1.f / (float)N_NODES;
    float4 sum4 = ((const float4*)g_stats)[64 + c4];
    float4 sq4  = ((const float4*)g_stats)[96 + c4];
    float4 gm4  = ((const float4*)gamma)[c4];
    float4 bt4  = ((const float4*)beta)[c4];
    float4 v = ((float4*)g_h)[i];
    float4 y;
    float m = sum4.x * inv_n, var = sq4.x * inv_n - m * m;
    y.x = fmaxf((v.x - m) * rsqrtf(var + BN_EPS) * gm4.x + bt4.x, 0.f);
    m = sum4.y * inv_n; var = sq4.y * inv_n - m * m;
    y.y = fmaxf((v.y - m) * rsqrtf(var + BN_EPS) * gm4.y + bt4.y, 0.f);
    m = sum4.z * inv_n; var = sq4.z * inv_n - m * m;
    y.z = fmaxf((v.z - m) * rsqrtf(var + BN_EPS) * gm4.z + bt4.z, 0.f);
    m = sum4.w * inv_n; var = sq4.w * inv_n - m * m;
    y.w = fmaxf((v.w - m) * rsqrtf(var + BN_EPS) * gm4.w + bt4.w, 0.f);
    int b = load_index(batch, (unsigned)row, g_batch64);
    atomicAdd(((float4*)g_pool) + (b * 32 + c4), y);
}

__global__ void counts_kernel(const void* __restrict__ batch) {
    __shared__ int hist[NGRAPH];
    if (threadIdx.x < NGRAPH) hist[threadIdx.x] = 0;
    __syncthreads();
    int is64 = g_batch64;
    for (int i = blockIdx.x * 256 + threadIdx.x; i < N_NODES; i += gridDim.x * 256)
        atomicAdd(&hist[load_index(batch, (unsigned)i, is64)], 1);
    __syncthreads();
    if (threadIdx.x < NGRAPH && hist[threadIdx.x])
        atomicAdd(&g_cnt[threadIdx.x], (float)hist[threadIdx.x]);
}

__global__ void head_kernel(const float* __restrict__ Wlin, const float* __restrict__ blin,
                            float* __restrict__ out) {
    __shared__ float p[HID];
    __shared__ float logit[NCLS];
    int g = blockIdx.x;
    float c = fmaxf(g_cnt[g], 1.0f);
    p[threadIdx.x] = g_pool[g * HID + threadIdx.x] / c;
    __syncthreads();
    if (threadIdx.x < NCLS) {
        float s = blin[threadIdx.x];
        for (int k = 0; k < HID; k++) s += p[k] * Wlin[k * NCLS + threadIdx.x];
        logit[threadIdx.x] = s;
    }
    __syncthreads();
    if (threadIdx.x == 0) {
        float m = -1e30f;
        for (int i = 0; i < NCLS; i++) m = fmaxf(m, logit[i]);
        float se = 0.f;
        for (int i = 0; i < NCLS; i++) se += expf(logit[i] - m);
        float lse = m + logf(se);
        for (int i = 0; i < NCLS; i++) out[g * NCLS + i] = logit[i] - lse;
    }
}

// ================= launch =================
extern "C" void kernel_launch(void* const* d_in, const int* in_sizes, int n_in,
                              void* d_out, int out_size) {
    const float* x     = (const float*)d_in[0];
    const void*  eidx  = d_in[1];
    const void*  batch = d_in[2];
    const float* W1a = (const float*)d_in[3];
    const float* b1a = (const float*)d_in[4];
    const float* W1b = (const float*)d_in[5];
    const float* b1b = (const float*)d_in[6];
    const float* gamma1 = (const float*)d_in[7];
    const float* beta1  = (const float*)d_in[8];
    const float* W2a = (const float*)d_in[9];
    const float* b2a = (const float*)d_in[10];
    const float* W2b = (const float*)d_in[11];
    const float* b2b = (const float*)d_in[12];
    const float* gamma2 = (const float*)d_in[13];
    const float* beta2  = (const float*)d_in[14];
    const float* Wlin = (const float*)d_in[15];
    const float* blin = (const float*)d_in[16];
    float* out = (float*)d_out;

    float *p_agg, *p_h;
    cudaGetSymbolAddress((void**)&p_agg, g_agg);
    cudaGetSymbolAddress((void**)&p_h,   g_h);

    const int SMEM_MLP = (3 * 128 * SA + 256) * sizeof(float);   // ~204 KB
    cudaFuncSetAttribute(mlp_kernel, cudaFuncAttributeMaxDynamicSharedMemorySize, SMEM_MLP);

    const int EW_BLOCKS  = (N_NODES * 32 + 255) / 256;
    const int EDGE_BLOCKS = (N_EDGES + 255) / 256;
    const int MLP_BLOCKS = (N_NODES + MT - 1) / MT;
    const int GATHER_BLOCKS = (N_NODES + 7) / 8;

    detect_kernel<<<1, 32>>>(eidx, batch);
    zero_kernel<<<(N_NODES + 255) / 256, 256>>>();

    // ---- CSR build (once; shared by both convs) ----
    hist_kernel<<<EDGE_BLOCKS, 256>>>(eidx);
    chunksum_kernel<<<NCHUNK, 256>>>();
    bscan_kernel<<<1, 128>>>();
    chunkscan_kernel<<<NCHUNK, 256>>>();
    fill_kernel<<<EDGE_BLOCKS, 256>>>(eidx);

    // ---- conv1 ----
    gather_kernel<<<GATHER_BLOCKS, 256>>>(x, p_agg);
    mlp_kernel<<<MLP_BLOCKS, 256, SMEM_MLP>>>(p_agg, W1a, b1a, W1b, b1b, p_h);
    colstats_kernel<<<1024, 128>>>(p_h, 0);
    bn_apply1_kernel<<<EW_BLOCKS, 256>>>(gamma1, beta1);

    // ---- conv2 ----
    gather_kernel<<<GATHER_BLOCKS, 256>>>(p_h, p_agg);
    mlp_kernel<<<MLP_BLOCKS, 256, SMEM_MLP>>>(p_agg, W2a, b2a, W2b, b2b, p_h);
    colstats_kernel<<<1024, 128>>>(p_h, 2 * HID);
    counts_kernel<<<128, 256>>>(batch);
    bn_apply2_kernel<<<EW_BLOCKS, 256>>>(gamma2, beta2, batch);

    // ---- head ----
    head_kernel<<<NGRAPH, HID>>>(Wlin, blin, out);
}

// round 8
// speedup vs baseline: 1.4171x; 1.0093x over previous
#include <cuda_runtime.h>
#include <cstdint>

#define N_NODES 100000
#define N_EDGES 800000
#define HID     128
#define NGRAPH  128
#define NCLS    10
#define BN_EPS  1e-5f
#define MT      128        // M rows per MLP block tile
#define SA      132        // smem stride (floats), conflict-free for fragment gathers
#define CHUNK   1024
#define NCHUNK  ((N_NODES + CHUNK - 1) / CHUNK)   // 98

// ---------------- scratch (allocation-free: device globals) ----------------
__device__ __align__(16) float g_agg[N_NODES * HID];   // self + neighbor sum
__device__ __align__(16) float g_h  [N_NODES * HID];   // conv output
__device__ __align__(16) float g_stats[4 * HID];       // [sum1, sumsq1, sum2, sumsq2]
__device__ __align__(16) float g_pool[NGRAPH * HID];
__device__ __align__(16) float g_bn1s[HID];            // BN1 scale per column
__device__ __align__(16) float g_bn1t[HID];            // BN1 shift per column
__device__            float g_cnt[NGRAPH];
__device__ int g_idx64;
__device__ int g_batch64;
// CSR scratch
__device__ int g_deg[N_NODES];
__device__ int g_rowptr[N_NODES + 1];
__device__ int g_cursor[N_NODES];
__device__ int g_esrc[N_EDGES];
__device__ int g_bsum[NCHUNK];
__device__ int g_boff[NCHUNK];

// ---------------- helpers ----------------
__device__ __forceinline__ uint32_t f2tf(float f) {
    uint32_t u;
    asm("cvt.rna.tf32.f32 %0, %1;" : "=r"(u) : "f"(f));
    return u;
}
__device__ __forceinline__ void mma_tf32(float* c, const uint32_t* a, const uint32_t* b) {
    asm volatile(
        "mma.sync.aligned.m16n8k8.row.col.f32.tf32.tf32.f32 "
        "{%0,%1,%2,%3}, {%4,%5,%6,%7}, {%8,%9}, {%0,%1,%2,%3};"
        : "+f"(c[0]), "+f"(c[1]), "+f"(c[2]), "+f"(c[3])
        : "r"(a[0]), "r"(a[1]), "r"(a[2]), "r"(a[3]), "r"(b[0]), "r"(b[1]));
}

// ---------------- dtype detection (parallel: one warp, ballot) ----------------
__global__ void detect_kernel(const void* eidx, const void* batch) {
    int lane = threadIdx.x & 31;
    const long long* p = (const long long*)eidx;
    long long v0 = p[lane];
    long long v1 = p[32 + lane];
    bool ok = (v0 >= 0 && v0 < N_NODES && v1 >= 0 && v1 < N_NODES);
    ok = __all_sync(0xFFFFFFFFu, ok);
    // batch is sorted; mid-array entries are nonzero under both encodings,
    // and mid int64-reads stay in bounds even if the buffer is int32-sized.
    const long long* q = (const long long*)batch;
    int base = N_NODES / 2 - 64;
    long long b0 = q[base + lane];
    long long b1 = q[base + 32 + lane];
    bool ok2 = (b0 >= 0 && b0 < NGRAPH && b1 >= 0 && b1 < NGRAPH);
    ok2 = __all_sync(0xFFFFFFFFu, ok2);
    if (lane == 0) { g_idx64 = ok ? 1 : 0; g_batch64 = ok2 ? 1 : 0; }
}
__device__ __forceinline__ int load_index(const void* p, unsigned i, int is64) {
    return is64 ? (int)((const long long*)p)[i] : ((const int*)p)[i];
}

__global__ void zero_kernel() {
    int i = blockIdx.x * blockDim.x + threadIdx.x;
    if (i < NGRAPH * HID) g_pool[i] = 0.f;
    if (i < 4 * HID)      g_stats[i] = 0.f;
    if (i < NGRAPH)       g_cnt[i] = 0.f;
    if (i < N_NODES)      g_deg[i] = 0;
}

// ================= CSR build (once per launch; graph shared by both convs) =================
__global__ void hist_kernel(const void* __restrict__ eidx) {
    int e = blockIdx.x * 256 + threadIdx.x;
    if (e >= N_EDGES) return;
    int d = load_index(eidx, N_EDGES + (unsigned)e, g_idx64);
    atomicAdd(&g_deg[d], 1);
}

__global__ void chunksum_kernel() {
    __shared__ int red[256];
    int b = blockIdx.x, t = threadIdx.x;
    int base = b * CHUNK;
    int s = 0;
#pragma unroll
    for (int i = 0; i < CHUNK / 256; i++) {
        int idx = base + t + i * 256;
        if (idx < N_NODES) s += g_deg[idx];
    }
    red[t] = s;
    __syncthreads();
#pragma unroll
    for (int off = 128; off > 0; off >>= 1) {
        if (t < off) red[t] += red[t + off];
        __syncthreads();
    }
    if (t == 0) g_bsum[b] = red[0];
}

__global__ void bscan_kernel() {
    __shared__ int sb[128];
    int t = threadIdx.x;
    sb[t] = (t < NCHUNK) ? g_bsum[t] : 0;
    __syncthreads();
#pragma unroll
    for (int off = 1; off < 128; off <<= 1) {
        int v = (t >= off) ? sb[t - off] : 0;
        __syncthreads();
        sb[t] += v;
        __syncthreads();
    }
    if (t < NCHUNK) g_boff[t] = (t == 0) ? 0 : sb[t - 1];
    if (t == 0) g_rowptr[N_NODES] = N_EDGES;
}

__global__ void chunkscan_kernel() {
    __shared__ int red[256];
    int b = blockIdx.x, t = threadIdx.x;
    int base = b * CHUNK + t * 4;
    int d[4], s = 0;
#pragma unroll
    for (int q = 0; q < 4; q++) {
        int idx = base + q;
        d[q] = (idx < N_NODES) ? g_deg[idx] : 0;
        s += d[q];
    }
    red[t] = s;
    __syncthreads();
#pragma unroll
    for (int off = 1; off < 256; off <<= 1) {
        int v = (t >= off) ? red[t - off] : 0;
        __syncthreads();
        red[t] += v;
        __syncthreads();
    }
    int run = g_boff[b] + ((t == 0) ? 0 : red[t - 1]);
#pragma unroll
    for (int q = 0; q < 4; q++) {
        int idx = base + q;
        if (idx < N_NODES) {
            g_rowptr[idx] = run;
            g_cursor[idx] = run;
            run += d[q];
        }
    }
}

__global__ void fill_kernel(const void* __restrict__ eidx) {
    int e = blockIdx.x * 256 + threadIdx.x;
    if (e >= N_EDGES) return;
    int is64 = g_idx64;
    int s = load_index(eidx, (unsigned)e, is64);
    int d = load_index(eidx, N_EDGES + (unsigned)e, is64);
    int pos = atomicAdd(&g_cursor[d], 1);
    g_esrc[pos] = s;
}

// ================= BN1 scale/shift precompute (after colstats of conv1) =================
__global__ void bn1par_kernel(const float* __restrict__ gamma, const float* __restrict__ beta) {
    int f = threadIdx.x;
    const float inv_n = 1.f / (float)N_NODES;
    float m = g_stats[f] * inv_n;
    float var = g_stats[HID + f] * inv_n - m * m;
    float sc = gamma[f] * rsqrtf(var + BN_EPS);
    g_bn1s[f] = sc;
    g_bn1t[f] = beta[f] - m * sc;
}

// ================= gather aggregation (optionally with fused BN1+relu) =================
// out[d] = T(feat[d]) + sum_{j in CSR(d)} T(feat[src_j]),  T = relu(bn1(.)) if BN else identity
template <bool BN>
__global__ void gather_kernel(const float* __restrict__ feat, float* __restrict__ out) {
    int n = blockIdx.x * 8 + (threadIdx.x >> 5);
    if (n >= N_NODES) return;
    int lane = threadIdx.x & 31;
    float4 sc, sh;
    if (BN) {
        sc = ((const float4*)g_bn1s)[lane];
        sh = ((const float4*)g_bn1t)[lane];
    }
    const float4* f4 = (const float4*)feat;
    float4 v = __ldg(&f4[(size_t)n * 32 + lane]);   // self term
    float4 acc;
    if (BN) {
        acc.x = fmaxf(v.x * sc.x + sh.x, 0.f);
        acc.y = fmaxf(v.y * sc.y + sh.y, 0.f);
        acc.z = fmaxf(v.z * sc.z + sh.z, 0.f);
        acc.w = fmaxf(v.w * sc.w + sh.w, 0.f);
    } else {
        acc = v;
    }
    int beg = g_rowptr[n], end = g_rowptr[n + 1];
    for (int j = beg; j < end; j++) {
        int s = g_esrc[j];
        float4 u = __ldg(&f4[(size_t)s * 32 + lane]);
        if (BN) {
            acc.x += fmaxf(u.x * sc.x + sh.x, 0.f);
            acc.y += fmaxf(u.y * sc.y + sh.y, 0.f);
            acc.z += fmaxf(u.z * sc.z + sh.z, 0.f);
            acc.w += fmaxf(u.w * sc.w + sh.w, 0.f);
        } else {
            acc.x += u.x; acc.y += u.y; acc.z += u.z; acc.w += u.w;
        }
    }
    ((float4*)out)[(size_t)n * 32 + lane] = acc;
}

// ================= fused MLP: C = relu(A@Wa + ba)@Wb + bb  (mma.sync tf32) =================
__device__ __forceinline__ void warp_gemm_tf32(const float* __restrict__ sAp,
                                               const float* __restrict__ sW,
                                               int wm, int wn, int g, int tg,
                                               float acc[2][8][4])
{
#pragma unroll 4
    for (int kt = 0; kt < 16; kt++) {
        int k0 = kt * 8;
        uint32_t a[2][4];
#pragma unroll
        for (int mi = 0; mi < 2; mi++) {
            int r = wm + mi * 16 + g;
            a[mi][0] = __float_as_uint(sAp[(r    ) * SA + k0 + tg    ]);
            a[mi][1] = __float_as_uint(sAp[(r + 8) * SA + k0 + tg    ]);
            a[mi][2] = __float_as_uint(sAp[(r    ) * SA + k0 + tg + 4]);
            a[mi][3] = __float_as_uint(sAp[(r + 8) * SA + k0 + tg + 4]);
        }
        uint32_t b[8][2];
#pragma unroll
        for (int ni = 0; ni < 8; ni++) {
            int n = wn + ni * 8 + g;
            b[ni][0] = __float_as_uint(sW[(k0 + tg    ) * SA + n]);
            b[ni][1] = __float_as_uint(sW[(k0 + tg + 4) * SA + n]);
        }
#pragma unroll
        for (int mi = 0; mi < 2; mi++)
#pragma unroll
            for (int ni = 0; ni < 8; ni++)
                mma_tf32(acc[mi][ni], a[mi], b[ni]);
    }
}

__global__ void __launch_bounds__(256, 1) mlp_kernel(
    const float* __restrict__ A, const float* __restrict__ Wa, const float* __restrict__ ba,
    const float* __restrict__ Wb, const float* __restrict__ bb, float* __restrict__ C)
{
    extern __shared__ float sm[];
    float* sAp = sm;
    float* sWa = sm + 128 * SA;
    float* sWb = sWa + 128 * SA;
    float* sBa = sWb + 128 * SA;
    float* sBb = sBa + 128;

    int t = threadIdx.x;
    int wid = t >> 5, lane = t & 31, g = lane >> 2, tg = lane & 3;
    int wm = (wid & 3) * 32, wn = (wid >> 2) * 64;
    int row0 = blockIdx.x * MT;

    if (t < 128) { sBa[t] = ba[t]; sBb[t] = bb[t]; }

    {
        const float4* A4  = (const float4*)A;
        const float4* Wa4 = (const float4*)Wa;
        const float4* Wb4 = (const float4*)Wb;
#pragma unroll
        for (int i = 0; i < 16; i++) {
            int idx = t + i * 256;
            int r = idx >> 5, c4 = idx & 31;
            float4 v = (row0 + r < N_NODES) ? A4[(size_t)(row0 + r) * 32 + c4]
                                            : make_float4(0.f, 0.f, 0.f, 0.f);
            *(uint4*)&sAp[r * SA + c4 * 4] = make_uint4(f2tf(v.x), f2tf(v.y), f2tf(v.z), f2tf(v.w));
            float4 wa = Wa4[idx];
            *(uint4*)&sWa[r * SA + c4 * 4] = make_uint4(f2tf(wa.x), f2tf(wa.y), f2tf(wa.z), f2tf(wa.w));
            float4 wb = Wb4[idx];
            *(uint4*)&sWb[r * SA + c4 * 4] = make_uint4(f2tf(wb.x), f2tf(wb.y), f2tf(wb.z), f2tf(wb.w));
        }
    }
    __syncthreads();

    float acc[2][8][4];
#pragma unroll
    for (int mi = 0; mi < 2; mi++)
#pragma unroll
        for (int ni = 0; ni < 8; ni++)
#pragma unroll
            for (int q = 0; q < 4; q++) acc[mi][ni][q] = 0.f;

    warp_gemm_tf32(sAp, sWa, wm, wn, g, tg, acc);
    __syncthreads();

#pragma unroll
    for (int mi = 0; mi < 2; mi++) {
        int r0 = wm + mi * 16 + g;
#pragma unroll
        for (int ni = 0; ni < 8; ni++) {
            int c0 = wn + ni * 8 + 2 * tg;
            float bx = sBa[c0], by = sBa[c0 + 1];
            sAp[(r0    ) * SA + c0    ] = __uint_as_float(f2tf(fmaxf(acc[mi][ni][0] + bx, 0.f)));
            sAp[(r0    ) * SA + c0 + 1] = __uint_as_float(f2tf(fmaxf(acc[mi][ni][1] + by, 0.f)));
            sAp[(r0 + 8) * SA + c0    ] = __uint_as_float(f2tf(fmaxf(acc[mi][ni][2] + bx, 0.f)));
            sAp[(r0 + 8) * SA + c0 + 1] = __uint_as_float(f2tf(fmaxf(acc[mi][ni][3] + by, 0.f)));
        }
    }
    __syncthreads();

#pragma unroll
    for (int mi = 0; mi < 2; mi++)
#pragma unroll
        for (int ni = 0; ni < 8; ni++)
#pragma unroll
            for (int q = 0; q < 4; q++) acc[mi][ni][q] = 0.f;

    warp_gemm_tf32(sAp, sWb, wm, wn, g, tg, acc);

#pragma unroll
    for (int mi = 0; mi < 2; mi++) {
        int r0 = wm + mi * 16 + g;
#pragma unroll
        for (int ni = 0; ni < 8; ni++) {
            int c0 = wn + ni * 8 + 2 * tg;
            float bx = sBb[c0], by = sBb[c0 + 1];
            int rg0 = row0 + r0, rg1 = row0 + r0 + 8;
            if (rg0 < N_NODES) {
                float2 o = make_float2(acc[mi][ni][0] + bx, acc[mi][ni][1] + by);
                *(float2*)&C[(size_t)rg0 * HID + c0] = o;
            }
            if (rg1 < N_NODES) {
                float2 o = make_float2(acc[mi][ni][2] + bx, acc[mi][ni][3] + by);
                *(float2*)&C[(size_t)rg1 * HID + c0] = o;
            }
        }
    }
}

// ================= BN / stats / pool / head =================
__global__ void colstats_kernel(const float* __restrict__ h, int stat_off) {
    int f = threadIdx.x;
    float s = 0.f, q = 0.f;
    for (int r = blockIdx.x; r < N_NODES; r += gridDim.x) {
        float v = h[(size_t)r * HID + f];
        s += v; q += v * v;
    }
    atomicAdd(&g_stats[stat_off + f], s);
    atomicAdd(&g_stats[stat_off + HID + f], q);
}

__global__ void bn_apply2_kernel(const float* __restrict__ gamma, const float* __restrict__ beta,
                                 const void* __restrict__ batch) {
    int i = blockIdx.x * 256 + threadIdx.x;
    if (i >= N_NODES * 32) return;
    int c4 = i & 31;
    int row = i >> 5;
    const float inv_n = 1.f / (float)N_NODES;
    float4 sum4 = ((const float4*)g_stats)[64 + c4];
    float4 sq4  = ((const float4*)g_stats)[96 + c4];
    float4 gm4  = ((const float4*)gamma)[c4];
    float4 bt4  = ((const float4*)beta)[c4];
    float4 v = ((float4*)g_h)[i];
    float4 y;
    float m = sum4.x * inv_n, var = sq4.x * inv_n - m * m;
    y.x = fmaxf((v.x - m) * rsqrtf(var + BN_EPS) * gm4.x + bt4.x, 0.f);
    m = sum4.y * inv_n; var = sq4.y * inv_n - m * m;
    y.y = fmaxf((v.y - m) * rsqrtf(var + BN_EPS) * gm4.y + bt4.y, 0.f);
    m = sum4.z * inv_n; var = sq4.z * inv_n - m * m;
    y.z = fmaxf((v.z - m) * rsqrtf(var + BN_EPS) * gm4.z + bt4.z, 0.f);
    m = sum4.w * inv_n; var = sq4.w * inv_n - m * m;
    y.w = fmaxf((v.w - m) * rsqrtf(var + BN_EPS) * gm4.w + bt4.w, 0.f);
    int b = load_index(batch, (unsigned)row, g_batch64);
    atomicAdd(((float4*)g_pool) + (b * 32 + c4), y);
}

__global__ void counts_kernel(const void* __restrict__ batch) {
    __shared__ int hist[NGRAPH];
    if (threadIdx.x < NGRAPH) hist[threadIdx.x] = 0;
    __syncthreads();
    int is64 = g_batch64;
    for (int i = blockIdx.x * 256 + threadIdx.x; i < N_NODES; i += gridDim.x * 256)
        atomicAdd(&hist[load_index(batch, (unsigned)i, is64)], 1);
    __syncthreads();
    if (threadIdx.x < NGRAPH && hist[threadIdx.x])
        atomicAdd(&g_cnt[threadIdx.x], (float)hist[threadIdx.x]);
}

__global__ void head_kernel(const float* __restrict__ Wlin, const float* __restrict__ blin,
                            float* __restrict__ out) {
    __shared__ float p[HID];
    __shared__ float logit[NCLS];
    int g = blockIdx.x;
    float c = fmaxf(g_cnt[g], 1.0f);
    p[threadIdx.x] = g_pool[g * HID + threadIdx.x] / c;
    __syncthreads();
    if (threadIdx.x < NCLS) {
        float s = blin[threadIdx.x];
        for (int k = 0; k < HID; k++) s += p[k] * Wlin[k * NCLS + threadIdx.x];
        logit[threadIdx.x] = s;
    }
    __syncthreads();
    if (threadIdx.x == 0) {
        float m = -1e30f;
        for (int i = 0; i < NCLS; i++) m = fmaxf(m, logit[i]);
        float se = 0.f;
        for (int i = 0; i < NCLS; i++) se += expf(logit[i] - m);
        float lse = m + logf(se);
        for (int i = 0; i < NCLS; i++) out[g * NCLS + i] = logit[i] - lse;
    }
}

// ================= launch =================
extern "C" void kernel_launch(void* const* d_in, const int* in_sizes, int n_in,
                              void* d_out, int out_size) {
    const float* x     = (const float*)d_in[0];
    const void*  eidx  = d_in[1];
    const void*  batch = d_in[2];
    const float* W1a = (const float*)d_in[3];
    const float* b1a = (const float*)d_in[4];
    const float* W1b = (const float*)d_in[5];
    const float* b1b = (const float*)d_in[6];
    const float* gamma1 = (const float*)d_in[7];
    const float* beta1  = (const float*)d_in[8];
    const float* W2a = (const float*)d_in[9];
    const float* b2a = (const float*)d_in[10];
    const float* W2b = (const float*)d_in[11];
    const float* b2b = (const float*)d_in[12];
    const float* gamma2 = (const float*)d_in[13];
    const float* beta2  = (const float*)d_in[14];
    const float* Wlin = (const float*)d_in[15];
    const float* blin = (const float*)d_in[16];
    float* out = (float*)d_out;

    float *p_agg, *p_h;
    cudaGetSymbolAddress((void**)&p_agg, g_agg);
    cudaGetSymbolAddress((void**)&p_h,   g_h);

    const int SMEM_MLP = (3 * 128 * SA + 256) * sizeof(float);   // ~204 KB
    cudaFuncSetAttribute(mlp_kernel, cudaFuncAttributeMaxDynamicSharedMemorySize, SMEM_MLP);

    const int EW_BLOCKS  = (N_NODES * 32 + 255) / 256;
    const int EDGE_BLOCKS = (N_EDGES + 255) / 256;
    const int MLP_BLOCKS = (N_NODES + MT - 1) / MT;
    const int GATHER_BLOCKS = (N_NODES + 7) / 8;

    detect_kernel<<<1, 32>>>(eidx, batch);
    zero_kernel<<<(N_NODES + 255) / 256, 256>>>();

    // ---- CSR build (once; shared by both convs) ----
    hist_kernel<<<EDGE_BLOCKS, 256>>>(eidx);
    chunksum_kernel<<<NCHUNK, 256>>>();
    bscan_kernel<<<1, 128>>>();
    chunkscan_kernel<<<NCHUNK, 256>>>();
    fill_kernel<<<EDGE_BLOCKS, 256>>>(eidx);

    // ---- conv1 ----
    gather_kernel<false><<<GATHER_BLOCKS, 256>>>(x, p_agg);
    mlp_kernel<<<MLP_BLOCKS, 256, SMEM_MLP>>>(p_agg, W1a, b1a, W1b, b1b, p_h);
    colstats_kernel<<<1024, 128>>>(p_h, 0);
    bn1par_kernel<<<1, 128>>>(gamma1, beta1);

    // ---- conv2 (BN1+relu fused into the gather) ----
    gather_kernel<true><<<GATHER_BLOCKS, 256>>>(p_h, p_agg);
    mlp_kernel<<<MLP_BLOCKS, 256, SMEM_MLP>>>(p_agg, W2a, b2a, W2b, b2b, p_h);
    colstats_kernel<<<1024, 128>>>(p_h, 2 * HID);
    counts_kernel<<<128, 256>>>(batch);
    bn_apply2_kernel<<<EW_BLOCKS, 256>>>(gamma2, beta2, batch);

    // ---- head ----
    head_kernel<<<NGRAPH, HID>>>(Wlin, blin, out);
}

// round 12
// speedup vs baseline: 2.0309x; 1.4331x over previous
#include <cuda_runtime.h>
#include <cuda_fp16.h>
#include <cstdint>

#define N_NODES 100000
#define N_EDGES 800000
#define HID     128
#define NGRAPH  128
#define NCLS    10
#define BN_EPS  1e-5f
#define MT      128
#define SAH     136        // halves per A row in smem (conflict-free fragment loads)
#define SWH     136        // uint32 per packed-W row in smem
#define CHUNK   1024
#define NCHUNK  ((N_NODES + CHUNK - 1) / CHUNK)

// ---------------- scratch (allocation-free: device globals) ----------------
__device__ __align__(16) float g_agg[N_NODES * HID];
__device__ __align__(16) float g_h  [N_NODES * HID];
__device__ __align__(16) float g_stats[4 * HID];
__device__ __align__(16) float g_pool[NGRAPH * HID];
__device__ __align__(16) float g_bn1s[HID];
__device__ __align__(16) float g_bn1t[HID];
__device__            float g_cnt[NGRAPH];
__device__ int g_idx64;
__device__ int g_batch64;
__device__ int g_deg[N_NODES];
__device__ int g_rowptr[N_NODES + 1];
__device__ int g_cursor[N_NODES];
__device__ int g_esrc[N_EDGES];
__device__ int g_bsum[NCHUNK];
__device__ int g_boff[NCHUNK];

// ---------------- helpers ----------------
__device__ __forceinline__ void mma_f16(float* c, const uint32_t* a, const uint32_t* b) {
    asm volatile(
        "mma.sync.aligned.m16n8k16.row.col.f32.f16.f16.f32 "
        "{%0,%1,%2,%3}, {%4,%5,%6,%7}, {%8,%9}, {%0,%1,%2,%3};"
        : "+f"(c[0]), "+f"(c[1]), "+f"(c[2]), "+f"(c[3])
        : "r"(a[0]), "r"(a[1]), "r"(a[2]), "r"(a[3]), "r"(b[0]), "r"(b[1]));
}

// ---------------- dtype detection (parallel: one warp, ballot) ----------------
__global__ void detect_kernel(const void* eidx, const void* batch) {
    int lane = threadIdx.x & 31;
    const long long* p = (const long long*)eidx;
    long long v0 = p[lane];
    long long v1 = p[32 + lane];
    bool ok = (v0 >= 0 && v0 < N_NODES && v1 >= 0 && v1 < N_NODES);
    ok = __all_sync(0xFFFFFFFFu, ok);
    const long long* q = (const long long*)batch;
    int base = N_NODES / 2 - 64;
    long long b0 = q[base + lane];
    long long b1 = q[base + 32 + lane];
    bool ok2 = (b0 >= 0 && b0 < NGRAPH && b1 >= 0 && b1 < NGRAPH);
    ok2 = __all_sync(0xFFFFFFFFu, ok2);
    if (lane == 0) { g_idx64 = ok ? 1 : 0; g_batch64 = ok2 ? 1 : 0; }
}
__device__ __forceinline__ int load_index(const void* p, unsigned i, int is64) {
    return is64 ? (int)((const long long*)p)[i] : ((const int*)p)[i];
}

__global__ void zero_kernel() {
    int i = blockIdx.x * blockDim.x + threadIdx.x;
    if (i < NGRAPH * HID) g_pool[i] = 0.f;
    if (i < 4 * HID)      g_stats[i] = 0.f;
    if (i < NGRAPH)       g_cnt[i] = 0.f;
    if (i < N_NODES)      g_deg[i] = 0;
}

// ================= CSR build =================
__global__ void hist_kernel(const void* __restrict__ eidx) {
    int e = blockIdx.x * 256 + threadIdx.x;
    if (e >= N_EDGES) return;
    int d = load_index(eidx, N_EDGES + (unsigned)e, g_idx64);
    atomicAdd(&g_deg[d], 1);
}

__global__ void chunksum_kernel() {
    __shared__ int red[256];
    int b = blockIdx.x, t = threadIdx.x;
    int base = b * CHUNK;
    int s = 0;
#pragma unroll
    for (int i = 0; i < CHUNK / 256; i++) {
        int idx = base + t + i * 256;
        if (idx < N_NODES) s += g_deg[idx];
    }
    red[t] = s;
    __syncthreads();
#pragma unroll
    for (int off = 128; off > 0; off >>= 1) {
        if (t < off) red[t] += red[t + off];
        __syncthreads();
    }
    if (t == 0) g_bsum[b] = red[0];
}

__global__ void bscan_kernel() {
    __shared__ int sb[128];
    int t = threadIdx.x;
    sb[t] = (t < NCHUNK) ? g_bsum[t] : 0;
    __syncthreads();
#pragma unroll
    for (int off = 1; off < 128; off <<= 1) {
        int v = (t >= off) ? sb[t - off] : 0;
        __syncthreads();
        sb[t] += v;
        __syncthreads();
    }
    if (t < NCHUNK) g_boff[t] = (t == 0) ? 0 : sb[t - 1];
    if (t == 0) g_rowptr[N_NODES] = N_EDGES;
}

__global__ void chunkscan_kernel() {
    __shared__ int red[256];
    int b = blockIdx.x, t = threadIdx.x;
    int base = b * CHUNK + t * 4;
    int d[4], s = 0;
#pragma unroll
    for (int q = 0; q < 4; q++) {
        int idx = base + q;
        d[q] = (idx < N_NODES) ? g_deg[idx] : 0;
        s += d[q];
    }
    red[t] = s;
    __syncthreads();
#pragma unroll
    for (int off = 1; off < 256; off <<= 1) {
        int v = (t >= off) ? red[t - off] : 0;
        __syncthreads();
        red[t] += v;
        __syncthreads();
    }
    int run = g_boff[b] + ((t == 0) ? 0 : red[t - 1]);
#pragma unroll
    for (int q = 0; q < 4; q++) {
        int idx = base + q;
        if (idx < N_NODES) {
            g_rowptr[idx] = run;
            g_cursor[idx] = run;
            run += d[q];
        }
    }
}

__global__ void fill_kernel(const void* __restrict__ eidx) {
    int e = blockIdx.x * 256 + threadIdx.x;
    if (e >= N_EDGES) return;
    int is64 = g_idx64;
    int s = load_index(eidx, (unsigned)e, is64);
    int d = load_index(eidx, N_EDGES + (unsigned)e, is64);
    int pos = atomicAdd(&g_cursor[d], 1);
    g_esrc[pos] = s;
}

// ================= BN1 scale/shift precompute =================
__global__ void bn1par_kernel(const float* __restrict__ gamma, const float* __restrict__ beta) {
    int f = threadIdx.x;
    const float inv_n = 1.f / (float)N_NODES;
    float m = g_stats[f] * inv_n;
    float var = g_stats[HID + f] * inv_n - m * m;
    float sc = gamma[f] * rsqrtf(var + BN_EPS);
    g_bn1s[f] = sc;
    g_bn1t[f] = beta[f] - m * sc;
}

// ================= gather aggregation (optional fused BN1+relu) =================
template <bool BN>
__global__ void gather_kernel(const float* __restrict__ feat, float* __restrict__ out) {
    int n = blockIdx.x * 8 + (threadIdx.x >> 5);
    if (n >= N_NODES) return;
    int lane = threadIdx.x & 31;
    float4 sc, sh;
    if (BN) {
        sc = ((const float4*)g_bn1s)[lane];
        sh = ((const float4*)g_bn1t)[lane];
    }
    const float4* f4 = (const float4*)feat;
    float4 v = __ldg(&f4[(size_t)n * 32 + lane]);
    float4 acc;
    if (BN) {
        acc.x = fmaxf(v.x * sc.x + sh.x, 0.f);
        acc.y = fmaxf(v.y * sc.y + sh.y, 0.f);
        acc.z = fmaxf(v.z * sc.z + sh.z, 0.f);
        acc.w = fmaxf(v.w * sc.w + sh.w, 0.f);
    } else {
        acc = v;
    }
    int beg = g_rowptr[n], end = g_rowptr[n + 1];
    for (int j = beg; j < end; j++) {
        int s = g_esrc[j];
        float4 u = __ldg(&f4[(size_t)s * 32 + lane]);
        if (BN) {
            acc.x += fmaxf(u.x * sc.x + sh.x, 0.f);
            acc.y += fmaxf(u.y * sc.y + sh.y, 0.f);
            acc.z += fmaxf(u.z * sc.z + sh.z, 0.f);
            acc.w += fmaxf(u.w * sc.w + sh.w, 0.f);
        } else {
            acc.x += u.x; acc.y += u.y; acc.z += u.z; acc.w += u.w;
        }
    }
    ((float4*)out)[(size_t)n * 32 + lane] = acc;
}

// ================= fused MLP (fp16 mma m16n8k16) + fused column stats =================
// SMEM bytes: sA half[128*SAH]=34816 | sW2a u32[64*SWH]=34816 | sW2b =34816 |
//             sBa f32[128]=512 | sBb f32[128]=512 | sSum f32[128]=512 | sSq f32[128]=512
#define OFF_A    0
#define OFF_WA   34816
#define OFF_WB   69632
#define OFF_BA   104448
#define OFF_BB   104960
#define OFF_SUM  105472
#define OFF_SQ   105984
#define SMEM_MLP 106496

__device__ __forceinline__ void warp_gemm_f16(const __half* __restrict__ sA,
                                              const uint32_t* __restrict__ sW2,
                                              int wm, int wn, int g, int tg,
                                              float acc[2][8][4])
{
#pragma unroll
    for (int kt = 0; kt < 8; kt++) {
        int k0 = kt * 16;
        uint32_t a[2][4];
#pragma unroll
        for (int mi = 0; mi < 2; mi++) {
            int r = wm + mi * 16 + g;
            a[mi][0] = *(const uint32_t*)(sA + r * SAH + k0 + 2 * tg);
            a[mi][1] = *(const uint32_t*)(sA + (r + 8) * SAH + k0 + 2 * tg);
            a[mi][2] = *(const uint32_t*)(sA + r * SAH + k0 + 8 + 2 * tg);
            a[mi][3] = *(const uint32_t*)(sA + (r + 8) * SAH + k0 + 8 + 2 * tg);
        }
        uint32_t b[8][2];
        int kp0 = k0 / 2 + tg;
#pragma unroll
        for (int ni = 0; ni < 8; ni++) {
            int n = wn + ni * 8 + g;
            b[ni][0] = sW2[kp0 * SWH + n];
            b[ni][1] = sW2[(kp0 + 4) * SWH + n];
        }
#pragma unroll
        for (int mi = 0; mi < 2; mi++)
#pragma unroll
            for (int ni = 0; ni < 8; ni++)
                mma_f16(acc[mi][ni], a[mi], b[ni]);
    }
}

__global__ void __launch_bounds__(256, 2) mlp_kernel(
    const float* __restrict__ A, const float* __restrict__ Wa, const float* __restrict__ ba,
    const float* __restrict__ Wb, const float* __restrict__ bb, float* __restrict__ C,
    int stat_off)
{
    extern __shared__ char smraw[];
    __half*   sA   = (__half*)(smraw + OFF_A);
    uint32_t* sW2a = (uint32_t*)(smraw + OFF_WA);
    uint32_t* sW2b = (uint32_t*)(smraw + OFF_WB);
    float*    sBa  = (float*)(smraw + OFF_BA);
    float*    sBb  = (float*)(smraw + OFF_BB);
    float*    sSum = (float*)(smraw + OFF_SUM);
    float*    sSq  = (float*)(smraw + OFF_SQ);

    int t = threadIdx.x;
    int wid = t >> 5, lane = t & 31, g = lane >> 2, tg = lane & 3;
    int wm = (wid & 3) * 32, wn = (wid >> 2) * 64;
    int row0 = blockIdx.x * MT;

    if (t < 128) { sBa[t] = ba[t]; sBb[t] = bb[t]; sSum[t] = 0.f; sSq[t] = 0.f; }

    // ---- A tile: fp32 -> half ----
    {
        const float4* A4 = (const float4*)A;
#pragma unroll
        for (int i = 0; i < 16; i++) {
            int idx = t + i * 256;
            int r = idx >> 5, c4 = idx & 31;
            float4 v = (row0 + r < N_NODES) ? A4[(size_t)(row0 + r) * 32 + c4]
                                            : make_float4(0.f, 0.f, 0.f, 0.f);
            __half2 h01 = __floats2half2_rn(v.x, v.y);
            __half2 h23 = __floats2half2_rn(v.z, v.w);
            uint2 u = make_uint2(*(uint32_t*)&h01, *(uint32_t*)&h23);
            *(uint2*)(sA + r * SAH + c4 * 4) = u;
        }
    }
    // ---- W tiles: pack k-pairs: sW2[k/2][n] = (W[k][n], W[k+1][n]) as half2 ----
    {
        const float4* Wa4 = (const float4*)Wa;
        const float4* Wb4 = (const float4*)Wb;
#pragma unroll
        for (int i = 0; i < 8; i++) {
            int idx = t + i * 256;             // 0..2047
            int kp = idx >> 5, c4 = idx & 31;  // kp 0..63, n0 = c4*4
            float4 lo = Wa4[(2 * kp) * 32 + c4];
            float4 hi = Wa4[(2 * kp + 1) * 32 + c4];
            __half2 p0 = __floats2half2_rn(lo.x, hi.x);
            __half2 p1 = __floats2half2_rn(lo.y, hi.y);
            __half2 p2 = __floats2half2_rn(lo.z, hi.z);
            __half2 p3 = __floats2half2_rn(lo.w, hi.w);
            *(uint4*)(sW2a + kp * SWH + c4 * 4) =
                make_uint4(*(uint32_t*)&p0, *(uint32_t*)&p1, *(uint32_t*)&p2, *(uint32_t*)&p3);
            lo = Wb4[(2 * kp) * 32 + c4];
            hi = Wb4[(2 * kp + 1) * 32 + c4];
            p0 = __floats2half2_rn(lo.x, hi.x);
            p1 = __floats2half2_rn(lo.y, hi.y);
            p2 = __floats2half2_rn(lo.z, hi.z);
            p3 = __floats2half2_rn(lo.w, hi.w);
            *(uint4*)(sW2b + kp * SWH + c4 * 4) =
                make_uint4(*(uint32_t*)&p0, *(uint32_t*)&p1, *(uint32_t*)&p2, *(uint32_t*)&p3);
        }
    }
    __syncthreads();

    // ---- GEMM 1 ----
    float acc[2][8][4];
#pragma unroll
    for (int mi = 0; mi < 2; mi++)
#pragma unroll
        for (int ni = 0; ni < 8; ni++)
#pragma unroll
            for (int q = 0; q < 4; q++) acc[mi][ni][q] = 0.f;

    warp_gemm_f16(sA, sW2a, wm, wn, g, tg, acc);
    __syncthreads();

    // ---- epilogue 1: relu(H + ba) -> half back into sA ----
#pragma unroll
    for (int mi = 0; mi < 2; mi++) {
        int r0 = wm + mi * 16 + g;
#pragma unroll
        for (int ni = 0; ni < 8; ni++) {
            int c0 = wn + ni * 8 + 2 * tg;
            float bx = sBa[c0], by = sBa[c0 + 1];
            __half2 h0 = __floats2half2_rn(fmaxf(acc[mi][ni][0] + bx, 0.f),
                                           fmaxf(acc[mi][ni][1] + by, 0.f));
            __half2 h1 = __floats2half2_rn(fmaxf(acc[mi][ni][2] + bx, 0.f),
                                           fmaxf(acc[mi][ni][3] + by, 0.f));
            *(uint32_t*)(sA + r0 * SAH + c0) = *(uint32_t*)&h0;
            *(uint32_t*)(sA + (r0 + 8) * SAH + c0) = *(uint32_t*)&h1;
        }
    }
    __syncthreads();

    // ---- GEMM 2 ----
#pragma unroll
    for (int mi = 0; mi < 2; mi++)
#pragma unroll
        for (int ni = 0; ni < 8; ni++)
#pragma unroll
            for (int q = 0; q < 4; q++) acc[mi][ni][q] = 0.f;

    warp_gemm_f16(sA, sW2b, wm, wn, g, tg, acc);

    // ---- epilogue 2: out + bb -> global, with fused column sum/sumsq ----
#pragma unroll
    for (int ni = 0; ni < 8; ni++) {
        int c0 = wn + ni * 8 + 2 * tg;
        float bx = sBb[c0], by = sBb[c0 + 1];
        float s0 = 0.f, s1 = 0.f, q0 = 0.f, q1 = 0.f;
#pragma unroll
        for (int mi = 0; mi < 2; mi++) {
            int lr0 = wm + mi * 16 + g;
            int rg0 = row0 + lr0, rg1 = rg0 + 8;
            float ox = acc[mi][ni][0] + bx;
            float oy = acc[mi][ni][1] + by;
            float oz = acc[mi][ni][2] + bx;
            float ow = acc[mi][ni][3] + by;
            if (rg0 < N_NODES) {
                *(float2*)&C[(size_t)rg0 * HID + c0] = make_float2(ox, oy);
                s0 += ox; s1 += oy; q0 += ox * ox; q1 += oy * oy;
            }
            if (rg1 < N_NODES) {
                *(float2*)&C[(size_t)rg1 * HID + c0] = make_float2(oz, ow);
                s0 += oz; s1 += ow; q0 += oz * oz; q1 += ow * ow;
            }
        }
        // reduce over g lanes (stride 4): lanes 0..3 (g==0) end with column totals
#pragma unroll
        for (int off = 16; off >= 4; off >>= 1) {
            s0 += __shfl_down_sync(0xFFFFFFFFu, s0, off);
            s1 += __shfl_down_sync(0xFFFFFFFFu, s1, off);
            q0 += __shfl_down_sync(0xFFFFFFFFu, q0, off);
            q1 += __shfl_down_sync(0xFFFFFFFFu, q1, off);
        }
        if (lane < 4) {
            atomicAdd(&sSum[c0], s0);
            atomicAdd(&sSum[c0 + 1], s1);
            atomicAdd(&sSq[c0], q0);
            atomicAdd(&sSq[c0 + 1], q1);
        }
    }
    __syncthreads();
    if (t < 128) {
        atomicAdd(&g_stats[stat_off + t], sSum[t]);
        atomicAdd(&g_stats[stat_off + HID + t], sSq[t]);
    }
}

// ================= BN2 apply + pool / counts / head =================
__global__ void bn_apply2_kernel(const float* __restrict__ gamma, const float* __restrict__ beta,
                                 const void* __restrict__ batch) {
    int i = blockIdx.x * 256 + threadIdx.x;
    if (i >= N_NODES * 32) return;
    int c4 = i & 31;
    int row = i >> 5;
    const float inv_n = 1.f / (float)N_NODES;
    float4 sum4 = ((const float4*)g_stats)[64 + c4];
    float4 sq4  = ((const float4*)g_stats)[96 + c4];
    float4 gm4  = ((const float4*)gamma)[c4];
    float4 bt4  = ((const float4*)beta)[c4];
    float4 v = ((float4*)g_h)[i];
    float4 y;
    float m = sum4.x * inv_n, var = sq4.x * inv_n - m * m;
    y.x = fmaxf((v.x - m) * rsqrtf(var + BN_EPS) * gm4.x + bt4.x, 0.f);
    m = sum4.y * inv_n; var = sq4.y * inv_n - m * m;
    y.y = fmaxf((v.y - m) * rsqrtf(var + BN_EPS) * gm4.y + bt4.y, 0.f);
    m = sum4.z * inv_n; var = sq4.z * inv_n - m * m;
    y.z = fmaxf((v.z - m) * rsqrtf(var + BN_EPS) * gm4.z + bt4.z, 0.f);
    m = sum4.w * inv_n; var = sq4.w * inv_n - m * m;
    y.w = fmaxf((v.w - m) * rsqrtf(var + BN_EPS) * gm4.w + bt4.w, 0.f);
    int b = load_index(batch, (unsigned)row, g_batch64);
    atomicAdd(((float4*)g_pool) + (b * 32 + c4), y);
}

__global__ void counts_kernel(const void* __restrict__ batch) {
    __shared__ int hist[NGRAPH];
    if (threadIdx.x < NGRAPH) hist[threadIdx.x] = 0;
    __syncthreads();
    int is64 = g_batch64;
    for (int i = blockIdx.x * 256 + threadIdx.x; i < N_NODES; i += gridDim.x * 256)
        atomicAdd(&hist[load_index(batch, (unsigned)i, is64)], 1);
    __syncthreads();
    if (threadIdx.x < NGRAPH && hist[threadIdx.x])
        atomicAdd(&g_cnt[threadIdx.x], (float)hist[threadIdx.x]);
}

__global__ void head_kernel(const float* __restrict__ Wlin, const float* __restrict__ blin,
                            float* __restrict__ out) {
    __shared__ float p[HID];
    __shared__ float logit[NCLS];
    int g = blockIdx.x;
    float c = fmaxf(g_cnt[g], 1.0f);
    p[threadIdx.x] = g_pool[g * HID + threadIdx.x] / c;
    __syncthreads();
    if (threadIdx.x < NCLS) {
        float s = blin[threadIdx.x];
        for (int k = 0; k < HID; k++) s += p[k] * Wlin[k * NCLS + threadIdx.x];
        logit[threadIdx.x] = s;
    }
    __syncthreads();
    if (threadIdx.x == 0) {
        float m = -1e30f;
        for (int i = 0; i < NCLS; i++) m = fmaxf(m, logit[i]);
        float se = 0.f;
        for (int i = 0; i < NCLS; i++) se += expf(logit[i] - m);
        float lse = m + logf(se);
        for (int i = 0; i < NCLS; i++) out[g * NCLS + i] = logit[i] - lse;
    }
}

// ================= launch =================
extern "C" void kernel_launch(void* const* d_in, const int* in_sizes, int n_in,
                              void* d_out, int out_size) {
    const float* x     = (const float*)d_in[0];
    const void*  eidx  = d_in[1];
    const void*  batch = d_in[2];
    const float* W1a = (const float*)d_in[3];
    const float* b1a = (const float*)d_in[4];
    const float* W1b = (const float*)d_in[5];
    const float* b1b = (const float*)d_in[6];
    const float* gamma1 = (const float*)d_in[7];
    const float* beta1  = (const float*)d_in[8];
    const float* W2a = (const float*)d_in[9];
    const float* b2a = (const float*)d_in[10];
    const float* W2b = (const float*)d_in[11];
    const float* b2b = (const float*)d_in[12];
    const float* gamma2 = (const float*)d_in[13];
    const float* beta2  = (const float*)d_in[14];
    const float* Wlin = (const float*)d_in[15];
    const float* blin = (const float*)d_in[16];
    float* out = (float*)d_out;

    float *p_agg, *p_h;
    cudaGetSymbolAddress((void**)&p_agg, g_agg);
    cudaGetSymbolAddress((void**)&p_h,   g_h);

    cudaFuncSetAttribute(mlp_kernel, cudaFuncAttributeMaxDynamicSharedMemorySize, SMEM_MLP);

    const int EW_BLOCKS  = (N_NODES * 32 + 255) / 256;
    const int EDGE_BLOCKS = (N_EDGES + 255) / 256;
    const int MLP_BLOCKS = (N_NODES + MT - 1) / MT;
    const int GATHER_BLOCKS = (N_NODES + 7) / 8;

    detect_kernel<<<1, 32>>>(eidx, batch);
    zero_kernel<<<(N_NODES + 255) / 256, 256>>>();

    // ---- CSR build ----
    hist_kernel<<<EDGE_BLOCKS, 256>>>(eidx);
    chunksum_kernel<<<NCHUNK, 256>>>();
    bscan_kernel<<<1, 128>>>();
    chunkscan_kernel<<<NCHUNK, 256>>>();
    fill_kernel<<<EDGE_BLOCKS, 256>>>(eidx);

    // ---- conv1 (colstats fused into MLP epilogue) ----
    gather_kernel<false><<<GATHER_BLOCKS, 256>>>(x, p_agg);
    mlp_kernel<<<MLP_BLOCKS, 256, SMEM_MLP>>>(p_agg, W1a, b1a, W1b, b1b, p_h, 0);
    bn1par_kernel<<<1, 128>>>(gamma1, beta1);

    // ---- conv2 (BN1+relu fused into gather; colstats fused into MLP) ----
    gather_kernel<true><<<GATHER_BLOCKS, 256>>>(p_h, p_agg);
    mlp_kernel<<<MLP_BLOCKS, 256, SMEM_MLP>>>(p_agg, W2a, b2a, W2b, b2b, p_h, 2 * HID);
    counts_kernel<<<128, 256>>>(batch);
    bn_apply2_kernel<<<EW_BLOCKS, 256>>>(gamma2, beta2, batch);

    // ---- head ----
    head_kernel<<<NGRAPH, HID>>>(Wlin, blin, out);
}

// round 16
// speedup vs baseline: 2.2434x; 1.1046x over previous
#include <cuda_runtime.h>
#include <cuda_fp16.h>
#include <cstdint>

#define N_NODES 100000
#define N_EDGES 800000
#define HID     128
#define NGRAPH  128
#define NCLS    10
#define BN_EPS  1e-5f
#define MT      128
#define SAH     136        // halves per A row in smem
#define SWH     136        // uint32 per packed-W row in smem
#define CHUNK   1024
#define NCHUNK  ((N_NODES + CHUNK - 1) / CHUNK)

// ---------------- scratch (allocation-free: device globals) ----------------
__device__ __align__(16) __half g_xh  [N_NODES * HID];   // x in half
__device__ __align__(16) __half g_aggh[N_NODES * HID];   // gather output (half)
__device__ __align__(16) __half g_hh  [N_NODES * HID];   // conv output (half)
__device__ __align__(16) float g_stats[4 * HID];
__device__ __align__(16) float g_pool[NGRAPH * HID];
__device__ __align__(16) float g_bn1s[HID];
__device__ __align__(16) float g_bn1t[HID];
__device__            float g_cnt[NGRAPH];
__device__ int g_idx64;
__device__ int g_batch64;
__device__ int g_deg[N_NODES];
__device__ int g_rowptr[N_NODES + 1];
__device__ int g_cursor[N_NODES];
__device__ int g_esrc[N_EDGES];
__device__ int g_bsum[NCHUNK];
__device__ int g_boff[NCHUNK];

// ---------------- helpers ----------------
__device__ __forceinline__ void mma_f16(float* c, const uint32_t* a, const uint32_t* b) {
    asm volatile(
        "mma.sync.aligned.m16n8k16.row.col.f32.f16.f16.f32 "
        "{%0,%1,%2,%3}, {%4,%5,%6,%7}, {%8,%9}, {%0,%1,%2,%3};"
        : "+f"(c[0]), "+f"(c[1]), "+f"(c[2]), "+f"(c[3])
        : "r"(a[0]), "r"(a[1]), "r"(a[2]), "r"(a[3]), "r"(b[0]), "r"(b[1]));
}

// ---------------- dtype detection (parallel: one warp, ballot) ----------------
__global__ void detect_kernel(const void* eidx, const void* batch) {
    int lane = threadIdx.x & 31;
    const long long* p = (const long long*)eidx;
    long long v0 = p[lane];
    long long v1 = p[32 + lane];
    bool ok = (v0 >= 0 && v0 < N_NODES && v1 >= 0 && v1 < N_NODES);
    ok = __all_sync(0xFFFFFFFFu, ok);
    const long long* q = (const long long*)batch;
    int base = N_NODES / 2 - 64;
    long long b0 = q[base + lane];
    long long b1 = q[base + 32 + lane];
    bool ok2 = (b0 >= 0 && b0 < NGRAPH && b1 >= 0 && b1 < NGRAPH);
    ok2 = __all_sync(0xFFFFFFFFu, ok2);
    if (lane == 0) { g_idx64 = ok ? 1 : 0; g_batch64 = ok2 ? 1 : 0; }
}
__device__ __forceinline__ int load_index(const void* p, unsigned i, int is64) {
    return is64 ? (int)((const long long*)p)[i] : ((const int*)p)[i];
}

__global__ void zero_kernel() {
    int i = blockIdx.x * blockDim.x + threadIdx.x;
    if (i < NGRAPH * HID) g_pool[i] = 0.f;
    if (i < 4 * HID)      g_stats[i] = 0.f;
    if (i < NGRAPH)       g_cnt[i] = 0.f;
    if (i < N_NODES)      g_deg[i] = 0;
}

// ---------------- x -> half ----------------
__global__ void tohalf_kernel(const float4* __restrict__ src) {
    int i = blockIdx.x * 256 + threadIdx.x;
    if (i >= N_NODES * 32) return;
    float4 v = src[i];
    __half2 h01 = __floats2half2_rn(v.x, v.y);
    __half2 h23 = __floats2half2_rn(v.z, v.w);
    ((uint2*)g_xh)[i] = make_uint2(*(uint32_t*)&h01, *(uint32_t*)&h23);
}

// ================= CSR build =================
__global__ void hist_kernel(const void* __restrict__ eidx) {
    int e = blockIdx.x * 256 + threadIdx.x;
    if (e >= N_EDGES) return;
    int d = load_index(eidx, N_EDGES + (unsigned)e, g_idx64);
    atomicAdd(&g_deg[d], 1);
}

__global__ void chunksum_kernel() {
    __shared__ int red[256];
    int b = blockIdx.x, t = threadIdx.x;
    int base = b * CHUNK;
    int s = 0;
#pragma unroll
    for (int i = 0; i < CHUNK / 256; i++) {
        int idx = base + t + i * 256;
        if (idx < N_NODES) s += g_deg[idx];
    }
    red[t] = s;
    __syncthreads();
#pragma unroll
    for (int off = 128; off > 0; off >>= 1) {
        if (t < off) red[t] += red[t + off];
        __syncthreads();
    }
    if (t == 0) g_bsum[b] = red[0];
}

__global__ void bscan_kernel() {
    __shared__ int sb[128];
    int t = threadIdx.x;
    sb[t] = (t < NCHUNK) ? g_bsum[t] : 0;
    __syncthreads();
#pragma unroll
    for (int off = 1; off < 128; off <<= 1) {
        int v = (t >= off) ? sb[t - off] : 0;
        __syncthreads();
        sb[t] += v;
        __syncthreads();
    }
    if (t < NCHUNK) g_boff[t] = (t == 0) ? 0 : sb[t - 1];
    if (t == 0) g_rowptr[N_NODES] = N_EDGES;
}

__global__ void chunkscan_kernel() {
    __shared__ int red[256];
    int b = blockIdx.x, t = threadIdx.x;
    int base = b * CHUNK + t * 4;
    int d[4], s = 0;
#pragma unroll
    for (int q = 0; q < 4; q++) {
        int idx = base + q;
        d[q] = (idx < N_NODES) ? g_deg[idx] : 0;
        s += d[q];
    }
    red[t] = s;
    __syncthreads();
#pragma unroll
    for (int off = 1; off < 256; off <<= 1) {
        int v = (t >= off) ? red[t - off] : 0;
        __syncthreads();
        red[t] += v;
        __syncthreads();
    }
    int run = g_boff[b] + ((t == 0) ? 0 : red[t - 1]);
#pragma unroll
    for (int q = 0; q < 4; q++) {
        int idx = base + q;
        if (idx < N_NODES) {
            g_rowptr[idx] = run;
            g_cursor[idx] = run;
            run += d[q];
        }
    }
}

__global__ void fill_kernel(const void* __restrict__ eidx) {
    int e = blockIdx.x * 256 + threadIdx.x;
    if (e >= N_EDGES) return;
    int is64 = g_idx64;
    int s = load_index(eidx, (unsigned)e, is64);
    int d = load_index(eidx, N_EDGES + (unsigned)e, is64);
    int pos = atomicAdd(&g_cursor[d], 1);
    g_esrc[pos] = s;
}

// ================= BN1 scale/shift precompute =================
__global__ void bn1par_kernel(const float* __restrict__ gamma, const float* __restrict__ beta) {
    int f = threadIdx.x;
    const float inv_n = 1.f / (float)N_NODES;
    float m = g_stats[f] * inv_n;
    float var = g_stats[HID + f] * inv_n - m * m;
    float sc = gamma[f] * rsqrtf(var + BN_EPS);
    g_bn1s[f] = sc;
    g_bn1t[f] = beta[f] - m * sc;
}

// ================= gather aggregation on half features (fp32 accum) =================
// out[d] = T(feat[d]) + sum_j T(feat[src_j]); T = relu(bn1(.)) if BN
template <bool BN>
__global__ void gather_kernel(const __half* __restrict__ feat, __half* __restrict__ out) {
    int n = blockIdx.x * 8 + (threadIdx.x >> 5);
    if (n >= N_NODES) return;
    int lane = threadIdx.x & 31;
    float4 sc, sh;
    if (BN) {
        sc = ((const float4*)g_bn1s)[lane];
        sh = ((const float4*)g_bn1t)[lane];
    }
    const uint2* f2 = (const uint2*)feat;   // 4 halves per element
    uint2 u = __ldg(&f2[(size_t)n * 32 + lane]);
    float2 a01 = __half22float2(*(__half2*)&u.x);
    float2 a23 = __half22float2(*(__half2*)&u.y);
    float4 acc;
    if (BN) {
        acc.x = fmaxf(a01.x * sc.x + sh.x, 0.f);
        acc.y = fmaxf(a01.y * sc.y + sh.y, 0.f);
        acc.z = fmaxf(a23.x * sc.z + sh.z, 0.f);
        acc.w = fmaxf(a23.y * sc.w + sh.w, 0.f);
    } else {
        acc = make_float4(a01.x, a01.y, a23.x, a23.y);
    }
    int beg = g_rowptr[n], end = g_rowptr[n + 1];
    for (int j = beg; j < end; j++) {
        int s = g_esrc[j];
        uint2 w = __ldg(&f2[(size_t)s * 32 + lane]);
        float2 b01 = __half22float2(*(__half2*)&w.x);
        float2 b23 = __half22float2(*(__half2*)&w.y);
        if (BN) {
            acc.x += fmaxf(b01.x * sc.x + sh.x, 0.f);
            acc.y += fmaxf(b01.y * sc.y + sh.y, 0.f);
            acc.z += fmaxf(b23.x * sc.z + sh.z, 0.f);
            acc.w += fmaxf(b23.y * sc.w + sh.w, 0.f);
        } else {
            acc.x += b01.x; acc.y += b01.y; acc.z += b23.x; acc.w += b23.y;
        }
    }
    __half2 o01 = __floats2half2_rn(acc.x, acc.y);
    __half2 o23 = __floats2half2_rn(acc.z, acc.w);
    ((uint2*)out)[(size_t)n * 32 + lane] = make_uint2(*(uint32_t*)&o01, *(uint32_t*)&o23);
}

// ================= fused MLP (fp16 mma) + fused column stats =================
#define OFF_A    0
#define OFF_WA   34816
#define OFF_WB   69632
#define OFF_BA   104448
#define OFF_BB   104960
#define OFF_SUM  105472
#define OFF_SQ   105984
#define SMEM_MLP 106496

__device__ __forceinline__ void warp_gemm_f16(const __half* __restrict__ sA,
                                              const uint32_t* __restrict__ sW2,
                                              int wm, int wn, int g, int tg,
                                              float acc[2][8][4])
{
#pragma unroll
    for (int kt = 0; kt < 8; kt++) {
        int k0 = kt * 16;
        uint32_t a[2][4];
#pragma unroll
        for (int mi = 0; mi < 2; mi++) {
            int r = wm + mi * 16 + g;
            a[mi][0] = *(const uint32_t*)(sA + r * SAH + k0 + 2 * tg);
            a[mi][1] = *(const uint32_t*)(sA + (r + 8) * SAH + k0 + 2 * tg);
            a[mi][2] = *(const uint32_t*)(sA + r * SAH + k0 + 8 + 2 * tg);
            a[mi][3] = *(const uint32_t*)(sA + (r + 8) * SAH + k0 + 8 + 2 * tg);
        }
        uint32_t b[8][2];
        int kp0 = k0 / 2 + tg;
#pragma unroll
        for (int ni = 0; ni < 8; ni++) {
            int n = wn + ni * 8 + g;
            b[ni][0] = sW2[kp0 * SWH + n];
            b[ni][1] = sW2[(kp0 + 4) * SWH + n];
        }
#pragma unroll
        for (int mi = 0; mi < 2; mi++)
#pragma unroll
            for (int ni = 0; ni < 8; ni++)
                mma_f16(acc[mi][ni], a[mi], b[ni]);
    }
}

__global__ void __launch_bounds__(256, 2) mlp_kernel(
    const __half* __restrict__ A, const float* __restrict__ Wa, const float* __restrict__ ba,
    const float* __restrict__ Wb, const float* __restrict__ bb, __half* __restrict__ C,
    int stat_off)
{
    extern __shared__ char smraw[];
    __half*   sA   = (__half*)(smraw + OFF_A);
    uint32_t* sW2a = (uint32_t*)(smraw + OFF_WA);
    uint32_t* sW2b = (uint32_t*)(smraw + OFF_WB);
    float*    sBa  = (float*)(smraw + OFF_BA);
    float*    sBb  = (float*)(smraw + OFF_BB);
    float*    sSum = (float*)(smraw + OFF_SUM);
    float*    sSq  = (float*)(smraw + OFF_SQ);

    int t = threadIdx.x;
    int wid = t >> 5, lane = t & 31, g = lane >> 2, tg = lane & 3;
    int wm = (wid & 3) * 32, wn = (wid >> 2) * 64;
    int row0 = blockIdx.x * MT;

    if (t < 128) { sBa[t] = ba[t]; sBb[t] = bb[t]; sSum[t] = 0.f; sSq[t] = 0.f; }

    // ---- A tile: direct half copy ----
    {
        const uint2* A2 = (const uint2*)A;
#pragma unroll
        for (int i = 0; i < 16; i++) {
            int idx = t + i * 256;
            int r = idx >> 5, c4 = idx & 31;
            uint2 u = (row0 + r < N_NODES) ? A2[(size_t)(row0 + r) * 32 + c4]
                                           : make_uint2(0u, 0u);
            *(uint2*)(sA + r * SAH + c4 * 4) = u;
        }
    }
    // ---- W tiles: pack k-pairs ----
    {
        const float4* Wa4 = (const float4*)Wa;
        const float4* Wb4 = (const float4*)Wb;
#pragma unroll
        for (int i = 0; i < 8; i++) {
            int idx = t + i * 256;
            int kp = idx >> 5, c4 = idx & 31;
            float4 lo = Wa4[(2 * kp) * 32 + c4];
            float4 hi = Wa4[(2 * kp + 1) * 32 + c4];
            __half2 p0 = __floats2half2_rn(lo.x, hi.x);
            __half2 p1 = __floats2half2_rn(lo.y, hi.y);
            __half2 p2 = __floats2half2_rn(lo.z, hi.z);
            __half2 p3 = __floats2half2_rn(lo.w, hi.w);
            *(uint4*)(sW2a + kp * SWH + c4 * 4) =
                make_uint4(*(uint32_t*)&p0, *(uint32_t*)&p1, *(uint32_t*)&p2, *(uint32_t*)&p3);
            lo = Wb4[(2 * kp) * 32 + c4];
            hi = Wb4[(2 * kp + 1) * 32 + c4];
            p0 = __floats2half2_rn(lo.x, hi.x);
            p1 = __floats2half2_rn(lo.y, hi.y);
            p2 = __floats2half2_rn(lo.z, hi.z);
            p3 = __floats2half2_rn(lo.w, hi.w);
            *(uint4*)(sW2b + kp * SWH + c4 * 4) =
                make_uint4(*(uint32_t*)&p0, *(uint32_t*)&p1, *(uint32_t*)&p2, *(uint32_t*)&p3);
        }
    }
    __syncthreads();

    // ---- GEMM 1 ----
    float acc[2][8][4];
#pragma unroll
    for (int mi = 0; mi < 2; mi++)
#pragma unroll
        for (int ni = 0; ni < 8; ni++)
#pragma unroll
            for (int q = 0; q < 4; q++) acc[mi][ni][q] = 0.f;

    warp_gemm_f16(sA, sW2a, wm, wn, g, tg, acc);
    __syncthreads();

    // ---- epilogue 1: relu(H + ba) -> half back into sA ----
#pragma unroll
    for (int mi = 0; mi < 2; mi++) {
        int r0 = wm + mi * 16 + g;
#pragma unroll
        for (int ni = 0; ni < 8; ni++) {
            int c0 = wn + ni * 8 + 2 * tg;
            float bx = sBa[c0], by = sBa[c0 + 1];
            __half2 h0 = __floats2half2_rn(fmaxf(acc[mi][ni][0] + bx, 0.f),
                                           fmaxf(acc[mi][ni][1] + by, 0.f));
            __half2 h1 = __floats2half2_rn(fmaxf(acc[mi][ni][2] + bx, 0.f),
                                           fmaxf(acc[mi][ni][3] + by, 0.f));
            *(uint32_t*)(sA + r0 * SAH + c0) = *(uint32_t*)&h0;
            *(uint32_t*)(sA + (r0 + 8) * SAH + c0) = *(uint32_t*)&h1;
        }
    }
    __syncthreads();

    // ---- GEMM 2 ----
#pragma unroll
    for (int mi = 0; mi < 2; mi++)
#pragma unroll
        for (int ni = 0; ni < 8; ni++)
#pragma unroll
            for (int q = 0; q < 4; q++) acc[mi][ni][q] = 0.f;

    warp_gemm_f16(sA, sW2b, wm, wn, g, tg, acc);

    // ---- epilogue 2: out + bb -> global (half), fused column sum/sumsq (fp32) ----
#pragma unroll
    for (int ni = 0; ni < 8; ni++) {
        int c0 = wn + ni * 8 + 2 * tg;
        float bx = sBb[c0], by = sBb[c0 + 1];
        float s0 = 0.f, s1 = 0.f, q0 = 0.f, q1 = 0.f;
#pragma unroll
        for (int mi = 0; mi < 2; mi++) {
            int lr0 = wm + mi * 16 + g;
            int rg0 = row0 + lr0, rg1 = rg0 + 8;
            float ox = acc[mi][ni][0] + bx;
            float oy = acc[mi][ni][1] + by;
            float oz = acc[mi][ni][2] + bx;
            float ow = acc[mi][ni][3] + by;
            if (rg0 < N_NODES) {
                __half2 h = __floats2half2_rn(ox, oy);
                *(uint32_t*)(C + (size_t)rg0 * HID + c0) = *(uint32_t*)&h;
                s0 += ox; s1 += oy; q0 += ox * ox; q1 += oy * oy;
            }
            if (rg1 < N_NODES) {
                __half2 h = __floats2half2_rn(oz, ow);
                *(uint32_t*)(C + (size_t)rg1 * HID + c0) = *(uint32_t*)&h;
                s0 += oz; s1 += ow; q0 += oz * oz; q1 += ow * ow;
            }
        }
#pragma unroll
        for (int off = 16; off >= 4; off >>= 1) {
            s0 += __shfl_down_sync(0xFFFFFFFFu, s0, off);
            s1 += __shfl_down_sync(0xFFFFFFFFu, s1, off);
            q0 += __shfl_down_sync(0xFFFFFFFFu, q0, off);
            q1 += __shfl_down_sync(0xFFFFFFFFu, q1, off);
        }
        if (lane < 4) {
            atomicAdd(&sSum[c0], s0);
            atomicAdd(&sSum[c0 + 1], s1);
            atomicAdd(&sSq[c0], q0);
            atomicAdd(&sSq[c0 + 1], q1);
        }
    }
    __syncthreads();
    if (t < 128) {
        atomicAdd(&g_stats[stat_off + t], sSum[t]);
        atomicAdd(&g_stats[stat_off + HID + t], sSq[t]);
    }
}

// ================= BN2 apply + pool (reads half h) =================
__global__ void bn_apply2_kernel(const float* __restrict__ gamma, const float* __restrict__ beta,
                                 const void* __restrict__ batch) {
    int i = blockIdx.x * 256 + threadIdx.x;
    if (i >= N_NODES * 32) return;
    int c4 = i & 31;
    int row = i >> 5;
    const float inv_n = 1.f / (float)N_NODES;
    float4 sum4 = ((const float4*)g_stats)[64 + c4];
    float4 sq4  = ((const float4*)g_stats)[96 + c4];
    float4 gm4  = ((const float4*)gamma)[c4];
    float4 bt4  = ((const float4*)beta)[c4];
    uint2 u = ((const uint2*)g_hh)[i];
    float2 v01 = __half22float2(*(__half2*)&u.x);
    float2 v23 = __half22float2(*(__half2*)&u.y);
    float4 y;
    float m = sum4.x * inv_n, var = sq4.x * inv_n - m * m;
    y.x = fmaxf((v01.x - m) * rsqrtf(var + BN_EPS) * gm4.x + bt4.x, 0.f);
    m = sum4.y * inv_n; var = sq4.y * inv_n - m * m;
    y.y = fmaxf((v01.y - m) * rsqrtf(var + BN_EPS) * gm4.y + bt4.y, 0.f);
    m = sum4.z * inv_n; var = sq4.z * inv_n - m * m;
    y.z = fmaxf((v23.x - m) * rsqrtf(var + BN_EPS) * gm4.z + bt4.z, 0.f);
    m = sum4.w * inv_n; var = sq4.w * inv_n - m * m;
    y.w = fmaxf((v23.y - m) * rsqrtf(var + BN_EPS) * gm4.w + bt4.w, 0.f);
    int b = load_index(batch, (unsigned)row, g_batch64);
    atomicAdd(((float4*)g_pool) + (b * 32 + c4), y);
}

__global__ void counts_kernel(const void* __restrict__ batch) {
    __shared__ int hist[NGRAPH];
    if (threadIdx.x < NGRAPH) hist[threadIdx.x] = 0;
    __syncthreads();
    int is64 = g_batch64;
    for (int i = blockIdx.x * 256 + threadIdx.x; i < N_NODES; i += gridDim.x * 256)
        atomicAdd(&hist[load_index(batch, (unsigned)i, is64)], 1);
    __syncthreads();
    if (threadIdx.x < NGRAPH && hist[threadIdx.x])
        atomicAdd(&g_cnt[threadIdx.x], (float)hist[threadIdx.x]);
}

__global__ void head_kernel(const float* __restrict__ Wlin, const float* __restrict__ blin,
                            float* __restrict__ out) {
    __shared__ float p[HID];
    __shared__ float logit[NCLS];
    int g = blockIdx.x;
    float c = fmaxf(g_cnt[g], 1.0f);
    p[threadIdx.x] = g_pool[g * HID + threadIdx.x] / c;
    __syncthreads();
    if (threadIdx.x < NCLS) {
        float s = blin[threadIdx.x];
        for (int k = 0; k < HID; k++) s += p[k] * Wlin[k * NCLS + threadIdx.x];
        logit[threadIdx.x] = s;
    }
    __syncthreads();
    if (threadIdx.x == 0) {
        float m = -1e30f;
        for (int i = 0; i < NCLS; i++) m = fmaxf(m, logit[i]);
        float se = 0.f;
        for (int i = 0; i < NCLS; i++) se += expf(logit[i] - m);
        float lse = m + logf(se);
        for (int i = 0; i < NCLS; i++) out[g * NCLS + i] = logit[i] - lse;
    }
}

// ================= launch =================
extern "C" void kernel_launch(void* const* d_in, const int* in_sizes, int n_in,
                              void* d_out, int out_size) {
    const float* x     = (const float*)d_in[0];
    const void*  eidx  = d_in[1];
    const void*  batch = d_in[2];
    const float* W1a = (const float*)d_in[3];
    const float* b1a = (const float*)d_in[4];
    const float* W1b = (const float*)d_in[5];
    const float* b1b = (const float*)d_in[6];
    const float* gamma1 = (const float*)d_in[7];
    const float* beta1  = (const float*)d_in[8];
    const float* W2a = (const float*)d_in[9];
    const float* b2a = (const float*)d_in[10];
    const float* W2b = (const float*)d_in[11];
    const float* b2b = (const float*)d_in[12];
    const float* gamma2 = (const float*)d_in[13];
    const float* beta2  = (const float*)d_in[14];
    const float* Wlin = (const float*)d_in[15];
    const float* blin = (const float*)d_in[16];
    float* out = (float*)d_out;

    __half *p_xh, *p_aggh, *p_hh;
    cudaGetSymbolAddress((void**)&p_xh,   g_xh);
    cudaGetSymbolAddress((void**)&p_aggh, g_aggh);
    cudaGetSymbolAddress((void**)&p_hh,   g_hh);

    cudaFuncSetAttribute(mlp_kernel, cudaFuncAttributeMaxDynamicSharedMemorySize, SMEM_MLP);

    const int EW_BLOCKS  = (N_NODES * 32 + 255) / 256;
    const int EDGE_BLOCKS = (N_EDGES + 255) / 256;
    const int MLP_BLOCKS = (N_NODES + MT - 1) / MT;
    const int GATHER_BLOCKS = (N_NODES + 7) / 8;

    detect_kernel<<<1, 32>>>(eidx, batch);
    zero_kernel<<<(N_NODES + 255) / 256, 256>>>();
    tohalf_kernel<<<EW_BLOCKS, 256>>>((const float4*)x);

    // ---- CSR build ----
    hist_kernel<<<EDGE_BLOCKS, 256>>>(eidx);
    chunksum_kernel<<<NCHUNK, 256>>>();
    bscan_kernel<<<1, 128>>>();
    chunkscan_kernel<<<NCHUNK, 256>>>();
    fill_kernel<<<EDGE_BLOCKS, 256>>>(eidx);

    // ---- conv1 ----
    gather_kernel<false><<<GATHER_BLOCKS, 256>>>(p_xh, p_aggh);
    mlp_kernel<<<MLP_BLOCKS, 256, SMEM_MLP>>>(p_aggh, W1a, b1a, W1b, b1b, p_hh, 0);
    bn1par_kernel<<<1, 128>>>(gamma1, beta1);

    // ---- conv2 (BN1+relu fused into gather) ----
    gather_kernel<true><<<GATHER_BLOCKS, 256>>>(p_hh, p_aggh);
    mlp_kernel<<<MLP_BLOCKS, 256, SMEM_MLP>>>(p_aggh, W2a, b2a, W2b, b2b, p_hh, 2 * HID);
    counts_kernel<<<128, 256>>>(batch);
    bn_apply2_kernel<<<EW_BLOCKS, 256>>>(gamma2, beta2, batch);

    // ---- head ----
    head_kernel<<<NGRAPH, HID>>>(Wlin, blin, out);
}